// round 7
// baseline (speedup 1.0000x reference)
#include <cuda_runtime.h>

#define B_    4096
#define NTOK  49
#define DIMC  192
#define NH    6
#define HD    32
#define NWIN  64

#define BM 128
#define BN 64
#define BK 16
#define NKIT (DIMC / BK)   // 12
#define APAD 132           // padded k-row stride for As/Bsd

typedef unsigned long long u64;

// Scratch (device globals — allocation-free per harness rules)
__device__ float g_q[(size_t)B_ * NH * NTOK * HD];   // q pre-scaled by hd^-0.5
__device__ float g_k[(size_t)B_ * NH * NTOK * HD];
__device__ float g_v[(size_t)B_ * NH * NTOK * HD];
__device__ float g_ctx[(size_t)B_ * NTOK * DIMC];

__device__ __forceinline__ void ffma2(u64& acc, u64 a, u64 b) {
    asm("fma.rn.f32x2 %0, %1, %2, %0;" : "+l"(acc) : "l"(a), "l"(b));
}

// ===========================================================================
// Double-buffered f32x2 GEMM core: y[m,j] = sum_k X[m,k] * W[j,k]  (+epilogue)
// CTA: 128 threads, tile BM=128 x BN=64, per-thread 8(M) x 8(N).
// As[buf][k][m] (pad 132), Bsd[buf][k][2j] duplicated pairs (pad 132).
// ===========================================================================
#define GEMM_MAINLOOP(XPTR, WPTR)                                              \
    __shared__ float As[2][BK][APAD];                                          \
    __shared__ float Bsd[2][BK][APAD];                                         \
    const int tid = threadIdx.x;                                               \
    const int m0  = blockIdx.y * BM;                                           \
    const int j0  = blockIdx.x * BN;                                           \
    const int ty  = tid >> 3;  /* 0..15 */                                     \
    const int tx  = tid & 7;   /* 0..7  */                                     \
    u64 acc2[4][8];                                                            \
    _Pragma("unroll") for (int i = 0; i < 4; i++)                              \
        _Pragma("unroll") for (int j = 0; j < 8; j++) acc2[i][j] = 0ull;       \
    float4 aR[4]; float4 bR[2];                                                \
    /* prologue load tile 0 */                                                 \
    _Pragma("unroll") for (int s = 0; s < 4; s++) {                            \
        const int f = s * 128 + tid; const int row = f >> 2; const int cg = f & 3; \
        aR[s] = *reinterpret_cast<const float4*>(XPTR + (size_t)(m0 + row) * DIMC + cg * 4); \
    }                                                                          \
    _Pragma("unroll") for (int s = 0; s < 2; s++) {                            \
        const int f = s * 128 + tid; const int row = f >> 2; const int cg = f & 3; \
        bR[s] = *reinterpret_cast<const float4*>(WPTR + (size_t)(j0 + row) * DIMC + cg * 4); \
    }                                                                          \
    _Pragma("unroll") for (int s = 0; s < 4; s++) {                            \
        const int f = s * 128 + tid; const int row = f >> 2; const int cg = f & 3; \
        As[0][cg * 4 + 0][row] = aR[s].x; As[0][cg * 4 + 1][row] = aR[s].y;    \
        As[0][cg * 4 + 2][row] = aR[s].z; As[0][cg * 4 + 3][row] = aR[s].w;    \
    }                                                                          \
    _Pragma("unroll") for (int s = 0; s < 2; s++) {                            \
        const int f = s * 128 + tid; const int row = f >> 2; const int cg = f & 3; \
        float2 d;                                                              \
        d.x = bR[s].x; d.y = bR[s].x; *reinterpret_cast<float2*>(&Bsd[0][cg*4+0][2*row]) = d; \
        d.x = bR[s].y; d.y = bR[s].y; *reinterpret_cast<float2*>(&Bsd[0][cg*4+1][2*row]) = d; \
        d.x = bR[s].z; d.y = bR[s].z; *reinterpret_cast<float2*>(&Bsd[0][cg*4+2][2*row]) = d; \
        d.x = bR[s].w; d.y = bR[s].w; *reinterpret_cast<float2*>(&Bsd[0][cg*4+3][2*row]) = d; \
    }                                                                          \
    __syncthreads();                                                           \
    for (int t = 0; t < NKIT; t++) {                                           \
        const int cur = t & 1;                                                 \
        if (t + 1 < NKIT) {                                                    \
            const int k0 = (t + 1) * BK;                                       \
            _Pragma("unroll") for (int s = 0; s < 4; s++) {                    \
                const int f = s * 128 + tid; const int row = f >> 2; const int cg = f & 3; \
                aR[s] = *reinterpret_cast<const float4*>(XPTR + (size_t)(m0 + row) * DIMC + k0 + cg * 4); \
            }                                                                  \
            _Pragma("unroll") for (int s = 0; s < 2; s++) {                    \
                const int f = s * 128 + tid; const int row = f >> 2; const int cg = f & 3; \
                bR[s] = *reinterpret_cast<const float4*>(WPTR + (size_t)(j0 + row) * DIMC + k0 + cg * 4); \
            }                                                                  \
        }                                                                      \
        _Pragma("unroll") for (int kk = 0; kk < BK; kk++) {                    \
            const u64* ap = reinterpret_cast<const u64*>(&As[cur][kk][ty * 8]); \
            const u64* bp = reinterpret_cast<const u64*>(&Bsd[cur][kk][tx * 16]); \
            u64 a2[4], b2[8];                                                  \
            _Pragma("unroll") for (int i = 0; i < 4; i++) a2[i] = ap[i];       \
            _Pragma("unroll") for (int j = 0; j < 8; j++) b2[j] = bp[j];       \
            _Pragma("unroll") for (int i = 0; i < 4; i++)                      \
                _Pragma("unroll") for (int j = 0; j < 8; j++)                  \
                    ffma2(acc2[i][j], a2[i], b2[j]);                           \
        }                                                                      \
        if (t + 1 < NKIT) {                                                    \
            const int nxt = (t + 1) & 1;                                       \
            _Pragma("unroll") for (int s = 0; s < 4; s++) {                    \
                const int f = s * 128 + tid; const int row = f >> 2; const int cg = f & 3; \
                As[nxt][cg * 4 + 0][row] = aR[s].x; As[nxt][cg * 4 + 1][row] = aR[s].y; \
                As[nxt][cg * 4 + 2][row] = aR[s].z; As[nxt][cg * 4 + 3][row] = aR[s].w; \
            }                                                                  \
            _Pragma("unroll") for (int s = 0; s < 2; s++) {                    \
                const int f = s * 128 + tid; const int row = f >> 2; const int cg = f & 3; \
                float2 d;                                                      \
                d.x = bR[s].x; d.y = bR[s].x; *reinterpret_cast<float2*>(&Bsd[nxt][cg*4+0][2*row]) = d; \
                d.x = bR[s].y; d.y = bR[s].y; *reinterpret_cast<float2*>(&Bsd[nxt][cg*4+1][2*row]) = d; \
                d.x = bR[s].z; d.y = bR[s].z; *reinterpret_cast<float2*>(&Bsd[nxt][cg*4+2][2*row]) = d; \
                d.x = bR[s].w; d.y = bR[s].w; *reinterpret_cast<float2*>(&Bsd[nxt][cg*4+3][2*row]) = d; \
            }                                                                  \
            __syncthreads();                                                   \
        }                                                                      \
    }

// ---------------------------------------------------------------------------
// Kernel 1: QKV GEMM + bias, scatter into g_q/g_k/g_v [B,H,N,hd], q *= scale
// ---------------------------------------------------------------------------
__global__ __launch_bounds__(128, 4)
void qkv_gemm_kernel(const float* __restrict__ X,
                     const float* __restrict__ W,
                     const float* __restrict__ bias)
{
    GEMM_MAINLOOP(X, W)

    const int jb = j0 + tx * 8;            // 8 consecutive output cols
    float bv[8];
#pragma unroll
    for (int j = 0; j < 8; j++) bv[j] = bias[jb + j];
    const int tt = jb / DIMC;              // 0=q, 1=k, 2=v (same for all 8)
    const int r  = jb - tt * DIMC;
    const int h  = r >> 5;
    const int d0 = r & 31;
    float* dstArr = (tt == 0) ? g_q : ((tt == 1) ? g_k : g_v);
    const float mul = (tt == 0) ? 0.17677669529663687f : 1.0f;

#pragma unroll
    for (int i = 0; i < 4; i++) {
#pragma unroll
        for (int e = 0; e < 2; e++) {
            const int m  = m0 + ty * 8 + 2 * i + e;
            const int bi = m / NTOK;
            const int ni = m - bi * NTOK;
            float v[8];
#pragma unroll
            for (int j = 0; j < 8; j++) {
                float2 p = *reinterpret_cast<float2*>(&acc2[i][j]);
                v[j] = ((e ? p.y : p.x) + bv[j]) * mul;
            }
            const size_t dst = ((size_t)(bi * NH + h) * NTOK + ni) * HD + d0;
            *reinterpret_cast<float4*>(&dstArr[dst])     = make_float4(v[0], v[1], v[2], v[3]);
            *reinterpret_cast<float4*>(&dstArr[dst + 4]) = make_float4(v[4], v[5], v[6], v[7]);
        }
    }
}

// ---------------------------------------------------------------------------
// Kernel 3: output projection  out = ctx @ proj_w.T + proj_b
// ---------------------------------------------------------------------------
__global__ __launch_bounds__(128, 4)
void proj_gemm_kernel(const float* __restrict__ W,
                      const float* __restrict__ bias,
                      float* __restrict__ out)
{
    const float* Xg = g_ctx;
    GEMM_MAINLOOP(Xg, W)

    const int jb = j0 + tx * 8;
    float bv[8];
#pragma unroll
    for (int j = 0; j < 8; j++) bv[j] = bias[jb + j];

#pragma unroll
    for (int i = 0; i < 4; i++) {
#pragma unroll
        for (int e = 0; e < 2; e++) {
            const int m = m0 + ty * 8 + 2 * i + e;
            float v[8];
#pragma unroll
            for (int j = 0; j < 8; j++) {
                float2 p = *reinterpret_cast<float2*>(&acc2[i][j]);
                v[j] = (e ? p.y : p.x) + bv[j];
            }
            *reinterpret_cast<float4*>(&out[(size_t)m * DIMC + jb])     = make_float4(v[0], v[1], v[2], v[3]);
            *reinterpret_cast<float4*>(&out[(size_t)m * DIMC + jb + 4]) = make_float4(v[4], v[5], v[6], v[7]);
        }
    }
}

// ---------------------------------------------------------------------------
// Kernel 2: per-(window, head) attention. f32x2 throughout.
// S kept DUPLICATED in SMEM so PV reads P-pairs with one LDS.64.
// ---------------------------------------------------------------------------
#define QSTR 34    // even stride for q/k/v rows (u64-aligned pairs)
#define SSTR 100   // duplicated S row stride

__global__ __launch_bounds__(256)
void attn_kernel(const float* __restrict__ mask,
                 const float* __restrict__ rpb,
                 const int*   __restrict__ rel_idx,
                 float* __restrict__ attn_out)
{
    __shared__ float qs[NTOK * QSTR];
    __shared__ float ks[NTOK * QSTR];
    __shared__ float vs[NTOK * QSTR];
    __shared__ float Sd[NTOK * SSTR];   // S duplicated: Sd[i*100 + 2j] == [.. +1]

    const int bh  = blockIdx.x;
    const int b   = bh / NH;
    const int h   = bh - b * NH;
    const int tid = threadIdx.x;

    // stage q/k/v as float2
    const size_t base2 = (size_t)bh * (NTOK * HD / 2);
    const float2* q2 = reinterpret_cast<const float2*>(g_q) + base2;
    const float2* k2 = reinterpret_cast<const float2*>(g_k) + base2;
    const float2* v2 = reinterpret_cast<const float2*>(g_v) + base2;
    for (int idx = tid; idx < NTOK * (HD / 2); idx += 256) {
        const int r = idx >> 4, dp = idx & 15;
        *reinterpret_cast<float2*>(&qs[r * QSTR + 2 * dp]) = q2[idx];
        *reinterpret_cast<float2*>(&ks[r * QSTR + 2 * dp]) = k2[idx];
        *reinterpret_cast<float2*>(&vs[r * QSTR + 2 * dp]) = v2[idx];
    }
    __syncthreads();

    // ---- S = q k^T + bias + mask : 2x2 register-blocked ----
    const float* mrow = mask + (size_t)(b & (NWIN - 1)) * (NTOK * NTOK);
    for (int it = tid; it < 25 * 25; it += 256) {
        const int ip = it / 25, jp = it - 25 * (it / 25);
        const int i0 = 2 * ip, i1 = i0 + 1;
        const int jj0 = 2 * jp, jj1 = jj0 + 1;
        const bool vi = (i1 < NTOK), vj = (jj1 < NTOK);
        const u64* qa = reinterpret_cast<const u64*>(&qs[i0 * QSTR]);
        const u64* qb = reinterpret_cast<const u64*>(&qs[(vi ? i1 : i0) * QSTR]);
        const u64* ka = reinterpret_cast<const u64*>(&ks[jj0 * QSTR]);
        const u64* kb = reinterpret_cast<const u64*>(&ks[(vj ? jj1 : jj0) * QSTR]);
        u64 a00 = 0, a01 = 0, a10 = 0, a11 = 0;
#pragma unroll
        for (int d = 0; d < HD / 2; d++) {
            const u64 q0v = qa[d], q1v = qb[d], k0v = ka[d], k1v = kb[d];
            ffma2(a00, q0v, k0v);
            ffma2(a01, q0v, k1v);
            ffma2(a10, q1v, k0v);
            ffma2(a11, q1v, k1v);
        }
        float2 f00 = *reinterpret_cast<float2*>(&a00);
        float2 f01 = *reinterpret_cast<float2*>(&a01);
        float2 f10 = *reinterpret_cast<float2*>(&a10);
        float2 f11 = *reinterpret_cast<float2*>(&a11);
        float s00 = f00.x + f00.y, s01 = f01.x + f01.y;
        float s10 = f10.x + f10.y, s11 = f11.x + f11.y;
        {
            const int idx = i0 * NTOK + jj0;
            s00 += rpb[rel_idx[idx] * NH + h] + mrow[idx];
            float2 dd; dd.x = s00; dd.y = s00;
            *reinterpret_cast<float2*>(&Sd[i0 * SSTR + 2 * jj0]) = dd;
        }
        if (vj) {
            const int idx = i0 * NTOK + jj1;
            s01 += rpb[rel_idx[idx] * NH + h] + mrow[idx];
            float2 dd; dd.x = s01; dd.y = s01;
            *reinterpret_cast<float2*>(&Sd[i0 * SSTR + 2 * jj1]) = dd;
        }
        if (vi) {
            const int idx = i1 * NTOK + jj0;
            s10 += rpb[rel_idx[idx] * NH + h] + mrow[idx];
            float2 dd; dd.x = s10; dd.y = s10;
            *reinterpret_cast<float2*>(&Sd[i1 * SSTR + 2 * jj0]) = dd;
            if (vj) {
                const int idx1 = i1 * NTOK + jj1;
                s11 += rpb[rel_idx[idx1] * NH + h] + mrow[idx1];
                float2 ee; ee.x = s11; ee.y = s11;
                *reinterpret_cast<float2*>(&Sd[i1 * SSTR + 2 * jj1]) = ee;
            }
        }
    }
    __syncthreads();

    // ---- row softmax (one warp per row, 8 warps striding) ----
    const int lane = tid & 31;
    const int wid  = tid >> 5;
    for (int i = wid; i < NTOK; i += 8) {
        float mval = -3.4e38f;
        for (int j = lane; j < NTOK; j += 32) mval = fmaxf(mval, Sd[i * SSTR + 2 * j]);
#pragma unroll
        for (int o = 16; o > 0; o >>= 1)
            mval = fmaxf(mval, __shfl_xor_sync(0xffffffffu, mval, o));
        float sum = 0.f;
        float ev[2];
        for (int j = lane, c = 0; j < NTOK; j += 32, c++) {
            const float e = expf(Sd[i * SSTR + 2 * j] - mval);
            ev[c] = e;
            sum += e;
        }
#pragma unroll
        for (int o = 16; o > 0; o >>= 1)
            sum += __shfl_xor_sync(0xffffffffu, sum, o);
        const float inv = 1.0f / sum;
        for (int j = lane, c = 0; j < NTOK; j += 32, c++) {
            const float pv = ev[c] * inv;
            float2 dd; dd.x = pv; dd.y = pv;
            *reinterpret_cast<float2*>(&Sd[i * SSTR + 2 * j]) = dd;
            if (attn_out)
                attn_out[(size_t)bh * (NTOK * NTOK) + i * NTOK + j] = pv;
        }
    }
    __syncthreads();

    // ---- ctx = P V : thread = (i-pair, d-pair) ----
    for (int it = tid; it < 25 * (HD / 2); it += 256) {
        const int ip = it >> 4, dp = it & 15;
        const int i0 = 2 * ip, i1 = i0 + 1;
        const bool vi = (i1 < NTOK);
        u64 c0 = 0, c1 = 0;
#pragma unroll 7
        for (int j = 0; j < NTOK; j++) {
            const u64 vv = *reinterpret_cast<const u64*>(&vs[j * QSTR + 2 * dp]);
            const u64 p0 = *reinterpret_cast<const u64*>(&Sd[i0 * SSTR + 2 * j]);
            ffma2(c0, p0, vv);
            if (vi) {
                const u64 p1 = *reinterpret_cast<const u64*>(&Sd[i1 * SSTR + 2 * j]);
                ffma2(c1, p1, vv);
            }
        }
        const size_t o0 = ((size_t)b * NTOK + i0) * DIMC + h * HD + 2 * dp;
        *reinterpret_cast<float2*>(&g_ctx[o0]) = *reinterpret_cast<float2*>(&c0);
        if (vi) {
            const size_t o1 = ((size_t)b * NTOK + i1) * DIMC + h * HD + 2 * dp;
            *reinterpret_cast<float2*>(&g_ctx[o1]) = *reinterpret_cast<float2*>(&c1);
        }
    }
}

// ---------------------------------------------------------------------------
// Launch
// ---------------------------------------------------------------------------
extern "C" void kernel_launch(void* const* d_in, const int* in_sizes, int n_in,
                              void* d_out, int out_size)
{
    const float* x      = (const float*)d_in[0];
    const float* mask   = (const float*)d_in[1];
    const float* qkv_w  = (const float*)d_in[2];
    const float* qkv_b  = (const float*)d_in[3];
    const float* proj_w = (const float*)d_in[4];
    const float* proj_b = (const float*)d_in[5];
    const float* rpb    = (const float*)d_in[6];
    const int*   relidx = (const int*)d_in[7];

    float* out = (float*)d_out;
    const long OUT_ELEMS  = (long)B_ * NTOK * DIMC;          // 38,535,168
    const long ATTN_ELEMS = (long)B_ * NH * NTOK * NTOK;     // 59,006,976
    float* attn_out = nullptr;
    if ((long)out_size >= OUT_ELEMS + ATTN_ELEMS) attn_out = out + OUT_ELEMS;

    qkv_gemm_kernel<<<dim3(576 / BN, (B_ * NTOK) / BM), 128>>>(x, qkv_w, qkv_b);
    attn_kernel<<<B_ * NH, 256>>>(mask, rpb, relidx, attn_out);
    proj_gemm_kernel<<<dim3(DIMC / BN, (B_ * NTOK) / BM), 128>>>(proj_w, proj_b, out);

    (void)in_sizes; (void)n_in;
}

// round 8
// speedup vs baseline: 2.9933x; 2.9933x over previous
#include <cuda_runtime.h>

#define B_    4096
#define NTOK  49
#define DIMC  192
#define NH    6
#define HD    32
#define NWIN  64

#define BM  128
#define BN  64
#define BKC 16
#define NCH (DIMC / BKC)   // 12 k-chunks
#define AST 24             // u32 stride per SMEM row (conflict-free fragments)

typedef unsigned long long u64;
typedef unsigned int u32;

// Scratch (device globals — allocation-free per harness rules)
__device__ float g_q[(size_t)B_ * NH * NTOK * HD];   // q pre-scaled by hd^-0.5
__device__ float g_k[(size_t)B_ * NH * NTOK * HD];
__device__ float g_v[(size_t)B_ * NH * NTOK * HD];
__device__ float g_ctx[(size_t)B_ * NTOK * DIMC];

__device__ __forceinline__ u32 f2tf(float f) {
    u32 r; asm("cvt.rna.tf32.f32 %0, %1;" : "=r"(r) : "f"(f)); return r;
}
__device__ __forceinline__ void mma_tf32(float* d, u32 a0, u32 a1, u32 a2, u32 a3,
                                         u32 b0, u32 b1) {
    asm volatile(
        "mma.sync.aligned.m16n8k8.row.col.f32.tf32.tf32.f32 "
        "{%0,%1,%2,%3}, {%4,%5,%6,%7}, {%8,%9}, {%0,%1,%2,%3};"
        : "+f"(d[0]), "+f"(d[1]), "+f"(d[2]), "+f"(d[3])
        : "r"(a0), "r"(a1), "r"(a2), "r"(a3), "r"(b0), "r"(b1));
}
__device__ __forceinline__ void ffma2(u64& acc, u64 a, u64 b) {
    asm("fma.rn.f32x2 %0, %1, %2, %0;" : "+l"(acc) : "l"(a), "l"(b));
}

// ===========================================================================
// tf32 MMA GEMM mainloop: acc[am][an][4] = X[m0:m0+128, :] @ W[j0:j0+64, :]^T
// SMEM k-pair-permuted: logical k c and c+4 of each 8-block stored adjacent
// (u32 slots 2*(4*blk+c) and +1) so fragments load with single LDS.64.
// ===========================================================================
#define TF32_GEMM_MAINLOOP(XPTR, WPTR)                                         \
    __shared__ __align__(16) u32 As[2][BM * AST];                              \
    __shared__ __align__(16) u32 Bs[2][BN * AST];                              \
    const int tid   = threadIdx.x;                                             \
    const int lane  = tid & 31;                                                \
    const int wid   = tid >> 5;                                                \
    const int m0    = blockIdx.y * BM;                                         \
    const int j0    = blockIdx.x * BN;                                         \
    const int ldrow = tid >> 2;          /* 0..31 */                           \
    const int ldcg  = tid & 3;           /* float4 index within 16-k chunk */  \
    const int ldoff = (ldcg & 1) + (ldcg >> 1) * 8;                            \
    const int frow  = lane >> 2;                                               \
    const int fcol  = lane & 3;                                                \
    const int wm    = wid * 32;                                                \
    float acc[2][8][4];                                                        \
    _Pragma("unroll") for (int i = 0; i < 2; i++)                              \
        _Pragma("unroll") for (int j = 0; j < 8; j++)                          \
            _Pragma("unroll") for (int e = 0; e < 4; e++) acc[i][j][e] = 0.f;  \
    float4 aR[4]; float4 bR[2];                                                \
    _Pragma("unroll") for (int s = 0; s < 4; s++)                              \
        aR[s] = *reinterpret_cast<const float4*>(                              \
            XPTR + (size_t)(m0 + s * 32 + ldrow) * DIMC + ldcg * 4);           \
    _Pragma("unroll") for (int s = 0; s < 2; s++)                              \
        bR[s] = *reinterpret_cast<const float4*>(                              \
            WPTR + (size_t)(j0 + s * 32 + ldrow) * DIMC + ldcg * 4);           \
    _Pragma("unroll") for (int s = 0; s < 4; s++) {                            \
        const int ba = (s * 32 + ldrow) * AST + ldoff;                         \
        As[0][ba + 0] = f2tf(aR[s].x); As[0][ba + 2] = f2tf(aR[s].y);          \
        As[0][ba + 4] = f2tf(aR[s].z); As[0][ba + 6] = f2tf(aR[s].w);          \
    }                                                                          \
    _Pragma("unroll") for (int s = 0; s < 2; s++) {                            \
        const int ba = (s * 32 + ldrow) * AST + ldoff;                         \
        Bs[0][ba + 0] = f2tf(bR[s].x); Bs[0][ba + 2] = f2tf(bR[s].y);          \
        Bs[0][ba + 4] = f2tf(bR[s].z); Bs[0][ba + 6] = f2tf(bR[s].w);          \
    }                                                                          \
    __syncthreads();                                                           \
    for (int t = 0; t < NCH; t++) {                                            \
        const int buf = t & 1;                                                 \
        if (t + 1 < NCH) {                                                     \
            const int kb = (t + 1) * BKC;                                      \
            _Pragma("unroll") for (int s = 0; s < 4; s++)                      \
                aR[s] = *reinterpret_cast<const float4*>(                      \
                    XPTR + (size_t)(m0 + s * 32 + ldrow) * DIMC + kb + ldcg * 4); \
            _Pragma("unroll") for (int s = 0; s < 2; s++)                      \
                bR[s] = *reinterpret_cast<const float4*>(                      \
                    WPTR + (size_t)(j0 + s * 32 + ldrow) * DIMC + kb + ldcg * 4); \
        }                                                                      \
        _Pragma("unroll") for (int ks = 0; ks < 2; ks++) {                     \
            uint2 afr[2][2];                                                   \
            _Pragma("unroll") for (int am = 0; am < 2; am++) {                 \
                const int r0 = wm + am * 16 + frow;                            \
                afr[am][0] = *reinterpret_cast<const uint2*>(                  \
                    &As[buf][r0 * AST + (ks * 4 + fcol) * 2]);                 \
                afr[am][1] = *reinterpret_cast<const uint2*>(                  \
                    &As[buf][(r0 + 8) * AST + (ks * 4 + fcol) * 2]);           \
            }                                                                  \
            uint2 bfr[8];                                                      \
            _Pragma("unroll") for (int an = 0; an < 8; an++)                   \
                bfr[an] = *reinterpret_cast<const uint2*>(                     \
                    &Bs[buf][(an * 8 + frow) * AST + (ks * 4 + fcol) * 2]);    \
            _Pragma("unroll") for (int am = 0; am < 2; am++)                   \
                _Pragma("unroll") for (int an = 0; an < 8; an++)               \
                    mma_tf32(acc[am][an],                                      \
                             afr[am][0].x, afr[am][1].x,                       \
                             afr[am][0].y, afr[am][1].y,                       \
                             bfr[an].x, bfr[an].y);                            \
        }                                                                      \
        if (t + 1 < NCH) {                                                     \
            const int nb = (t + 1) & 1;                                        \
            _Pragma("unroll") for (int s = 0; s < 4; s++) {                    \
                const int ba = (s * 32 + ldrow) * AST + ldoff;                 \
                As[nb][ba + 0] = f2tf(aR[s].x); As[nb][ba + 2] = f2tf(aR[s].y); \
                As[nb][ba + 4] = f2tf(aR[s].z); As[nb][ba + 6] = f2tf(aR[s].w); \
            }                                                                  \
            _Pragma("unroll") for (int s = 0; s < 2; s++) {                    \
                const int ba = (s * 32 + ldrow) * AST + ldoff;                 \
                Bs[nb][ba + 0] = f2tf(bR[s].x); Bs[nb][ba + 2] = f2tf(bR[s].y); \
                Bs[nb][ba + 4] = f2tf(bR[s].z); Bs[nb][ba + 6] = f2tf(bR[s].w); \
            }                                                                  \
            __syncthreads();                                                   \
        }                                                                      \
    }

// ---------------------------------------------------------------------------
// Kernel 1: QKV GEMM + bias, scatter into g_q/g_k/g_v [B,H,N,hd], q *= scale
// ---------------------------------------------------------------------------
__global__ __launch_bounds__(128, 3)
void qkv_gemm_kernel(const float* __restrict__ X,
                     const float* __restrict__ W,
                     const float* __restrict__ bias)
{
    TF32_GEMM_MAINLOOP(X, W)

    const int tt = j0 / DIMC;                 // 0=q, 1=k, 2=v (uniform per CTA)
    const int r0 = j0 - tt * DIMC;
    float* dstArr = (tt == 0) ? g_q : ((tt == 1) ? g_k : g_v);
    const float mul = (tt == 0) ? 0.17677669529663687f : 1.0f;

#pragma unroll
    for (int an = 0; an < 8; an++) {
        const int jc = an * 8 + fcol * 2;     // even → pair stays in one head
        const float bx = bias[j0 + jc];
        const float by = bias[j0 + jc + 1];
        const int c = r0 + jc;
        const int h = c >> 5;
        const int d = c & 31;
#pragma unroll
        for (int am = 0; am < 2; am++) {
#pragma unroll
            for (int rh = 0; rh < 2; rh++) {
                const int m  = m0 + wm + am * 16 + frow + rh * 8;
                const int bi = m / NTOK;
                const int ni = m - bi * NTOK;
                const size_t dst = ((size_t)(bi * NH + h) * NTOK + ni) * HD + d;
                float2 o;
                o.x = (acc[am][an][rh * 2 + 0] + bx) * mul;
                o.y = (acc[am][an][rh * 2 + 1] + by) * mul;
                *reinterpret_cast<float2*>(&dstArr[dst]) = o;
            }
        }
    }
}

// ---------------------------------------------------------------------------
// Kernel 3: output projection  out = ctx @ proj_w.T + proj_b
// ---------------------------------------------------------------------------
__global__ __launch_bounds__(128, 3)
void proj_gemm_kernel(const float* __restrict__ W,
                      const float* __restrict__ bias,
                      float* __restrict__ out)
{
    const float* Xg = g_ctx;
    TF32_GEMM_MAINLOOP(Xg, W)

#pragma unroll
    for (int an = 0; an < 8; an++) {
        const int jc = an * 8 + fcol * 2;
        const float bx = bias[j0 + jc];
        const float by = bias[j0 + jc + 1];
#pragma unroll
        for (int am = 0; am < 2; am++) {
#pragma unroll
            for (int rh = 0; rh < 2; rh++) {
                const int m = m0 + wm + am * 16 + frow + rh * 8;
                float2 o;
                o.x = acc[am][an][rh * 2 + 0] + bx;
                o.y = acc[am][an][rh * 2 + 1] + by;
                *reinterpret_cast<float2*>(&out[(size_t)m * DIMC + j0 + jc]) = o;
            }
        }
    }
}

// ---------------------------------------------------------------------------
// Kernel 2: per-(window, head) attention (unchanged from R6 — passing).
// ---------------------------------------------------------------------------
#define QSTR 34
#define SSTR 100

__global__ __launch_bounds__(256)
void attn_kernel(const float* __restrict__ mask,
                 const float* __restrict__ rpb,
                 const int*   __restrict__ rel_idx,
                 float* __restrict__ attn_out)
{
    __shared__ float qs[NTOK * QSTR];
    __shared__ float ks[NTOK * QSTR];
    __shared__ float vs[NTOK * QSTR];
    __shared__ float Sd[NTOK * SSTR];

    const int bh  = blockIdx.x;
    const int b   = bh / NH;
    const int h   = bh - b * NH;
    const int tid = threadIdx.x;

    const size_t base2 = (size_t)bh * (NTOK * HD / 2);
    const float2* q2 = reinterpret_cast<const float2*>(g_q) + base2;
    const float2* k2 = reinterpret_cast<const float2*>(g_k) + base2;
    const float2* v2 = reinterpret_cast<const float2*>(g_v) + base2;
    for (int idx = tid; idx < NTOK * (HD / 2); idx += 256) {
        const int r = idx >> 4, dp = idx & 15;
        *reinterpret_cast<float2*>(&qs[r * QSTR + 2 * dp]) = q2[idx];
        *reinterpret_cast<float2*>(&ks[r * QSTR + 2 * dp]) = k2[idx];
        *reinterpret_cast<float2*>(&vs[r * QSTR + 2 * dp]) = v2[idx];
    }
    __syncthreads();

    const float* mrow = mask + (size_t)(b & (NWIN - 1)) * (NTOK * NTOK);
    for (int it = tid; it < 25 * 25; it += 256) {
        const int ip = it / 25, jp = it - 25 * (it / 25);
        const int i0 = 2 * ip, i1 = i0 + 1;
        const int jj0 = 2 * jp, jj1 = jj0 + 1;
        const bool vi = (i1 < NTOK), vj = (jj1 < NTOK);
        const u64* qa = reinterpret_cast<const u64*>(&qs[i0 * QSTR]);
        const u64* qb = reinterpret_cast<const u64*>(&qs[(vi ? i1 : i0) * QSTR]);
        const u64* ka = reinterpret_cast<const u64*>(&ks[jj0 * QSTR]);
        const u64* kb = reinterpret_cast<const u64*>(&ks[(vj ? jj1 : jj0) * QSTR]);
        u64 a00 = 0, a01 = 0, a10 = 0, a11 = 0;
#pragma unroll
        for (int d = 0; d < HD / 2; d++) {
            const u64 q0v = qa[d], q1v = qb[d], k0v = ka[d], k1v = kb[d];
            ffma2(a00, q0v, k0v);
            ffma2(a01, q0v, k1v);
            ffma2(a10, q1v, k0v);
            ffma2(a11, q1v, k1v);
        }
        float2 f00 = *reinterpret_cast<float2*>(&a00);
        float2 f01 = *reinterpret_cast<float2*>(&a01);
        float2 f10 = *reinterpret_cast<float2*>(&a10);
        float2 f11 = *reinterpret_cast<float2*>(&a11);
        float s00 = f00.x + f00.y, s01 = f01.x + f01.y;
        float s10 = f10.x + f10.y, s11 = f11.x + f11.y;
        {
            const int idx = i0 * NTOK + jj0;
            s00 += rpb[rel_idx[idx] * NH + h] + mrow[idx];
            float2 dd; dd.x = s00; dd.y = s00;
            *reinterpret_cast<float2*>(&Sd[i0 * SSTR + 2 * jj0]) = dd;
        }
        if (vj) {
            const int idx = i0 * NTOK + jj1;
            s01 += rpb[rel_idx[idx] * NH + h] + mrow[idx];
            float2 dd; dd.x = s01; dd.y = s01;
            *reinterpret_cast<float2*>(&Sd[i0 * SSTR + 2 * jj1]) = dd;
        }
        if (vi) {
            const int idx = i1 * NTOK + jj0;
            s10 += rpb[rel_idx[idx] * NH + h] + mrow[idx];
            float2 dd; dd.x = s10; dd.y = s10;
            *reinterpret_cast<float2*>(&Sd[i1 * SSTR + 2 * jj0]) = dd;
            if (vj) {
                const int idx1 = i1 * NTOK + jj1;
                s11 += rpb[rel_idx[idx1] * NH + h] + mrow[idx1];
                float2 ee; ee.x = s11; ee.y = s11;
                *reinterpret_cast<float2*>(&Sd[i1 * SSTR + 2 * jj1]) = ee;
            }
        }
    }
    __syncthreads();

    const int lane = tid & 31;
    const int wid  = tid >> 5;
    for (int i = wid; i < NTOK; i += 8) {
        float mval = -3.4e38f;
        for (int j = lane; j < NTOK; j += 32) mval = fmaxf(mval, Sd[i * SSTR + 2 * j]);
#pragma unroll
        for (int o = 16; o > 0; o >>= 1)
            mval = fmaxf(mval, __shfl_xor_sync(0xffffffffu, mval, o));
        float sum = 0.f;
        float ev[2];
        for (int j = lane, c = 0; j < NTOK; j += 32, c++) {
            const float e = expf(Sd[i * SSTR + 2 * j] - mval);
            ev[c] = e;
            sum += e;
        }
#pragma unroll
        for (int o = 16; o > 0; o >>= 1)
            sum += __shfl_xor_sync(0xffffffffu, sum, o);
        const float inv = 1.0f / sum;
        for (int j = lane, c = 0; j < NTOK; j += 32, c++) {
            const float pv = ev[c] * inv;
            float2 dd; dd.x = pv; dd.y = pv;
            *reinterpret_cast<float2*>(&Sd[i * SSTR + 2 * j]) = dd;
            if (attn_out)
                attn_out[(size_t)bh * (NTOK * NTOK) + i * NTOK + j] = pv;
        }
    }
    __syncthreads();

    for (int it = tid; it < 25 * (HD / 2); it += 256) {
        const int ip = it >> 4, dp = it & 15;
        const int i0 = 2 * ip, i1 = i0 + 1;
        const bool vi = (i1 < NTOK);
        u64 c0 = 0, c1 = 0;
#pragma unroll 7
        for (int j = 0; j < NTOK; j++) {
            const u64 vv = *reinterpret_cast<const u64*>(&vs[j * QSTR + 2 * dp]);
            const u64 p0 = *reinterpret_cast<const u64*>(&Sd[i0 * SSTR + 2 * j]);
            ffma2(c0, p0, vv);
            if (vi) {
                const u64 p1 = *reinterpret_cast<const u64*>(&Sd[i1 * SSTR + 2 * j]);
                ffma2(c1, p1, vv);
            }
        }
        const size_t o0 = ((size_t)b * NTOK + i0) * DIMC + h * HD + 2 * dp;
        *reinterpret_cast<float2*>(&g_ctx[o0]) = *reinterpret_cast<float2*>(&c0);
        if (vi) {
            const size_t o1 = ((size_t)b * NTOK + i1) * DIMC + h * HD + 2 * dp;
            *reinterpret_cast<float2*>(&g_ctx[o1]) = *reinterpret_cast<float2*>(&c1);
        }
    }
}

// ---------------------------------------------------------------------------
// Launch
// ---------------------------------------------------------------------------
extern "C" void kernel_launch(void* const* d_in, const int* in_sizes, int n_in,
                              void* d_out, int out_size)
{
    const float* x      = (const float*)d_in[0];
    const float* mask   = (const float*)d_in[1];
    const float* qkv_w  = (const float*)d_in[2];
    const float* qkv_b  = (const float*)d_in[3];
    const float* proj_w = (const float*)d_in[4];
    const float* proj_b = (const float*)d_in[5];
    const float* rpb    = (const float*)d_in[6];
    const int*   relidx = (const int*)d_in[7];

    float* out = (float*)d_out;
    const long OUT_ELEMS  = (long)B_ * NTOK * DIMC;          // 38,535,168
    const long ATTN_ELEMS = (long)B_ * NH * NTOK * NTOK;     // 59,006,976
    float* attn_out = nullptr;
    if ((long)out_size >= OUT_ELEMS + ATTN_ELEMS) attn_out = out + OUT_ELEMS;

    qkv_gemm_kernel<<<dim3(576 / BN, (B_ * NTOK) / BM), 128>>>(x, qkv_w, qkv_b);
    attn_kernel<<<B_ * NH, 256>>>(mask, rpb, relidx, attn_out);
    proj_gemm_kernel<<<dim3(DIMC / BN, (B_ * NTOK) / BM), 128>>>(proj_w, proj_b, out);

    (void)in_sizes; (void)n_in;
}

// round 9
// speedup vs baseline: 2.9992x; 1.0020x over previous
#include <cuda_runtime.h>

#define B_    4096
#define NTOK  49
#define DIMC  192
#define NH    6
#define HD    32
#define NWIN  64

#define BM  128
#define BN  64
#define BKC 16
#define NCH (DIMC / BKC)   // 12 k-chunks
#define AST 24             // u32 stride per SMEM row (conflict-free fragments)

typedef unsigned long long u64;
typedef unsigned int u32;

// Scratch (device globals — allocation-free per harness rules)
__device__ float g_q[(size_t)B_ * NH * NTOK * HD];   // q pre-scaled by hd^-0.5
__device__ float g_k[(size_t)B_ * NH * NTOK * HD];
__device__ float g_v[(size_t)B_ * NH * NTOK * HD];
__device__ float g_ctx[(size_t)B_ * NTOK * DIMC];

__device__ __forceinline__ u32 f2tf(float f) {
    u32 r; asm("cvt.rna.tf32.f32 %0, %1;" : "=r"(r) : "f"(f)); return r;
}
__device__ __forceinline__ void mma_tf32(float* d, u32 a0, u32 a1, u32 a2, u32 a3,
                                         u32 b0, u32 b1) {
    asm volatile(
        "mma.sync.aligned.m16n8k8.row.col.f32.tf32.tf32.f32 "
        "{%0,%1,%2,%3}, {%4,%5,%6,%7}, {%8,%9}, {%0,%1,%2,%3};"
        : "+f"(d[0]), "+f"(d[1]), "+f"(d[2]), "+f"(d[3])
        : "r"(a0), "r"(a1), "r"(a2), "r"(a3), "r"(b0), "r"(b1));
}
__device__ __forceinline__ void ffma2(u64& acc, u64 a, u64 b) {
    asm("fma.rn.f32x2 %0, %1, %2, %0;" : "+l"(acc) : "l"(a), "l"(b));
}

// ===========================================================================
// tf32 MMA GEMM mainloop: acc[am][an][4] = X[m0:m0+128, :] @ W[j0:j0+64, :]^T
// SMEM k-pair-permuted: logical k c and c+4 of each 8-block stored adjacent
// (u32 slots 2*(4*blk+c) and +1) so fragments load with single LDS.64.
// ===========================================================================
#define TF32_GEMM_MAINLOOP(XPTR, WPTR)                                         \
    __shared__ __align__(16) u32 As[2][BM * AST];                              \
    __shared__ __align__(16) u32 Bs[2][BN * AST];                              \
    const int tid   = threadIdx.x;                                             \
    const int lane  = tid & 31;                                                \
    const int wid   = tid >> 5;                                                \
    const int m0    = blockIdx.y * BM;                                         \
    const int j0    = blockIdx.x * BN;                                         \
    const int ldrow = tid >> 2;          /* 0..31 */                           \
    const int ldcg  = tid & 3;           /* float4 index within 16-k chunk */  \
    const int ldoff = (ldcg & 1) + (ldcg >> 1) * 8;                            \
    const int frow  = lane >> 2;                                               \
    const int fcol  = lane & 3;                                                \
    const int wm    = wid * 32;                                                \
    float acc[2][8][4];                                                        \
    _Pragma("unroll") for (int i = 0; i < 2; i++)                              \
        _Pragma("unroll") for (int j = 0; j < 8; j++)                          \
            _Pragma("unroll") for (int e = 0; e < 4; e++) acc[i][j][e] = 0.f;  \
    float4 aR[4]; float4 bR[2];                                                \
    _Pragma("unroll") for (int s = 0; s < 4; s++)                              \
        aR[s] = *reinterpret_cast<const float4*>(                              \
            XPTR + (size_t)(m0 + s * 32 + ldrow) * DIMC + ldcg * 4);           \
    _Pragma("unroll") for (int s = 0; s < 2; s++)                              \
        bR[s] = *reinterpret_cast<const float4*>(                              \
            WPTR + (size_t)(j0 + s * 32 + ldrow) * DIMC + ldcg * 4);           \
    _Pragma("unroll") for (int s = 0; s < 4; s++) {                            \
        const int ba = (s * 32 + ldrow) * AST + ldoff;                         \
        As[0][ba + 0] = f2tf(aR[s].x); As[0][ba + 2] = f2tf(aR[s].y);          \
        As[0][ba + 4] = f2tf(aR[s].z); As[0][ba + 6] = f2tf(aR[s].w);          \
    }                                                                          \
    _Pragma("unroll") for (int s = 0; s < 2; s++) {                            \
        const int ba = (s * 32 + ldrow) * AST + ldoff;                         \
        Bs[0][ba + 0] = f2tf(bR[s].x); Bs[0][ba + 2] = f2tf(bR[s].y);          \
        Bs[0][ba + 4] = f2tf(bR[s].z); Bs[0][ba + 6] = f2tf(bR[s].w);          \
    }                                                                          \
    __syncthreads();                                                           \
    for (int t = 0; t < NCH; t++) {                                            \
        const int buf = t & 1;                                                 \
        if (t + 1 < NCH) {                                                     \
            const int kb = (t + 1) * BKC;                                      \
            _Pragma("unroll") for (int s = 0; s < 4; s++)                      \
                aR[s] = *reinterpret_cast<const float4*>(                      \
                    XPTR + (size_t)(m0 + s * 32 + ldrow) * DIMC + kb + ldcg * 4); \
            _Pragma("unroll") for (int s = 0; s < 2; s++)                      \
                bR[s] = *reinterpret_cast<const float4*>(                      \
                    WPTR + (size_t)(j0 + s * 32 + ldrow) * DIMC + kb + ldcg * 4); \
        }                                                                      \
        _Pragma("unroll") for (int ks = 0; ks < 2; ks++) {                     \
            uint2 afr[2][2];                                                   \
            _Pragma("unroll") for (int am = 0; am < 2; am++) {                 \
                const int r0 = wm + am * 16 + frow;                            \
                afr[am][0] = *reinterpret_cast<const uint2*>(                  \
                    &As[buf][r0 * AST + (ks * 4 + fcol) * 2]);                 \
                afr[am][1] = *reinterpret_cast<const uint2*>(                  \
                    &As[buf][(r0 + 8) * AST + (ks * 4 + fcol) * 2]);           \
            }                                                                  \
            uint2 bfr[8];                                                      \
            _Pragma("unroll") for (int an = 0; an < 8; an++)                   \
                bfr[an] = *reinterpret_cast<const uint2*>(                     \
                    &Bs[buf][(an * 8 + frow) * AST + (ks * 4 + fcol) * 2]);    \
            _Pragma("unroll") for (int am = 0; am < 2; am++)                   \
                _Pragma("unroll") for (int an = 0; an < 8; an++)               \
                    mma_tf32(acc[am][an],                                      \
                             afr[am][0].x, afr[am][1].x,                       \
                             afr[am][0].y, afr[am][1].y,                       \
                             bfr[an].x, bfr[an].y);                            \
        }                                                                      \
        if (t + 1 < NCH) {                                                     \
            const int nb = (t + 1) & 1;                                        \
            _Pragma("unroll") for (int s = 0; s < 4; s++) {                    \
                const int ba = (s * 32 + ldrow) * AST + ldoff;                 \
                As[nb][ba + 0] = f2tf(aR[s].x); As[nb][ba + 2] = f2tf(aR[s].y); \
                As[nb][ba + 4] = f2tf(aR[s].z); As[nb][ba + 6] = f2tf(aR[s].w); \
            }                                                                  \
            _Pragma("unroll") for (int s = 0; s < 2; s++) {                    \
                const int ba = (s * 32 + ldrow) * AST + ldoff;                 \
                Bs[nb][ba + 0] = f2tf(bR[s].x); Bs[nb][ba + 2] = f2tf(bR[s].y); \
                Bs[nb][ba + 4] = f2tf(bR[s].z); Bs[nb][ba + 6] = f2tf(bR[s].w); \
            }                                                                  \
            __syncthreads();                                                   \
        }                                                                      \
    }

// ---------------------------------------------------------------------------
// Kernel 1: QKV GEMM + bias, scatter into g_q/g_k/g_v [B,H,N,hd], q *= scale
// ---------------------------------------------------------------------------
__global__ __launch_bounds__(128, 3)
void qkv_gemm_kernel(const float* __restrict__ X,
                     const float* __restrict__ W,
                     const float* __restrict__ bias)
{
    TF32_GEMM_MAINLOOP(X, W)

    const int tt = j0 / DIMC;                 // 0=q, 1=k, 2=v (uniform per CTA)
    const int r0 = j0 - tt * DIMC;
    float* dstArr = (tt == 0) ? g_q : ((tt == 1) ? g_k : g_v);
    const float mul = (tt == 0) ? 0.17677669529663687f : 1.0f;

#pragma unroll
    for (int an = 0; an < 8; an++) {
        const int jc = an * 8 + fcol * 2;     // even → pair stays in one head
        const float bx = bias[j0 + jc];
        const float by = bias[j0 + jc + 1];
        const int c = r0 + jc;
        const int h = c >> 5;
        const int d = c & 31;
#pragma unroll
        for (int am = 0; am < 2; am++) {
#pragma unroll
            for (int rh = 0; rh < 2; rh++) {
                const int m  = m0 + wm + am * 16 + frow + rh * 8;
                const int bi = m / NTOK;
                const int ni = m - bi * NTOK;
                const size_t dst = ((size_t)(bi * NH + h) * NTOK + ni) * HD + d;
                float2 o;
                o.x = (acc[am][an][rh * 2 + 0] + bx) * mul;
                o.y = (acc[am][an][rh * 2 + 1] + by) * mul;
                *reinterpret_cast<float2*>(&dstArr[dst]) = o;
            }
        }
    }
}

// ---------------------------------------------------------------------------
// Kernel 3: output projection  out = ctx @ proj_w.T + proj_b
// ---------------------------------------------------------------------------
__global__ __launch_bounds__(128, 3)
void proj_gemm_kernel(const float* __restrict__ W,
                      const float* __restrict__ bias,
                      float* __restrict__ out)
{
    const float* Xg = g_ctx;
    TF32_GEMM_MAINLOOP(Xg, W)

#pragma unroll
    for (int an = 0; an < 8; an++) {
        const int jc = an * 8 + fcol * 2;
        const float bx = bias[j0 + jc];
        const float by = bias[j0 + jc + 1];
#pragma unroll
        for (int am = 0; am < 2; am++) {
#pragma unroll
            for (int rh = 0; rh < 2; rh++) {
                const int m = m0 + wm + am * 16 + frow + rh * 8;
                float2 o;
                o.x = acc[am][an][rh * 2 + 0] + bx;
                o.y = acc[am][an][rh * 2 + 1] + by;
                *reinterpret_cast<float2*>(&out[(size_t)m * DIMC + j0 + jc]) = o;
            }
        }
    }
}

// ---------------------------------------------------------------------------
// Kernel 2: per-(window, head) attention (unchanged from R6 — passing).
// ---------------------------------------------------------------------------
#define QSTR 34
#define SSTR 100

__global__ __launch_bounds__(256)
void attn_kernel(const float* __restrict__ mask,
                 const float* __restrict__ rpb,
                 const int*   __restrict__ rel_idx,
                 float* __restrict__ attn_out)
{
    __shared__ float qs[NTOK * QSTR];
    __shared__ float ks[NTOK * QSTR];
    __shared__ float vs[NTOK * QSTR];
    __shared__ float Sd[NTOK * SSTR];

    const int bh  = blockIdx.x;
    const int b   = bh / NH;
    const int h   = bh - b * NH;
    const int tid = threadIdx.x;

    const size_t base2 = (size_t)bh * (NTOK * HD / 2);
    const float2* q2 = reinterpret_cast<const float2*>(g_q) + base2;
    const float2* k2 = reinterpret_cast<const float2*>(g_k) + base2;
    const float2* v2 = reinterpret_cast<const float2*>(g_v) + base2;
    for (int idx = tid; idx < NTOK * (HD / 2); idx += 256) {
        const int r = idx >> 4, dp = idx & 15;
        *reinterpret_cast<float2*>(&qs[r * QSTR + 2 * dp]) = q2[idx];
        *reinterpret_cast<float2*>(&ks[r * QSTR + 2 * dp]) = k2[idx];
        *reinterpret_cast<float2*>(&vs[r * QSTR + 2 * dp]) = v2[idx];
    }
    __syncthreads();

    const float* mrow = mask + (size_t)(b & (NWIN - 1)) * (NTOK * NTOK);
    for (int it = tid; it < 25 * 25; it += 256) {
        const int ip = it / 25, jp = it - 25 * (it / 25);
        const int i0 = 2 * ip, i1 = i0 + 1;
        const int jj0 = 2 * jp, jj1 = jj0 + 1;
        const bool vi = (i1 < NTOK), vj = (jj1 < NTOK);
        const u64* qa = reinterpret_cast<const u64*>(&qs[i0 * QSTR]);
        const u64* qb = reinterpret_cast<const u64*>(&qs[(vi ? i1 : i0) * QSTR]);
        const u64* ka = reinterpret_cast<const u64*>(&ks[jj0 * QSTR]);
        const u64* kb = reinterpret_cast<const u64*>(&ks[(vj ? jj1 : jj0) * QSTR]);
        u64 a00 = 0, a01 = 0, a10 = 0, a11 = 0;
#pragma unroll
        for (int d = 0; d < HD / 2; d++) {
            const u64 q0v = qa[d], q1v = qb[d], k0v = ka[d], k1v = kb[d];
            ffma2(a00, q0v, k0v);
            ffma2(a01, q0v, k1v);
            ffma2(a10, q1v, k0v);
            ffma2(a11, q1v, k1v);
        }
        float2 f00 = *reinterpret_cast<float2*>(&a00);
        float2 f01 = *reinterpret_cast<float2*>(&a01);
        float2 f10 = *reinterpret_cast<float2*>(&a10);
        float2 f11 = *reinterpret_cast<float2*>(&a11);
        float s00 = f00.x + f00.y, s01 = f01.x + f01.y;
        float s10 = f10.x + f10.y, s11 = f11.x + f11.y;
        {
            const int idx = i0 * NTOK + jj0;
            s00 += rpb[rel_idx[idx] * NH + h] + mrow[idx];
            float2 dd; dd.x = s00; dd.y = s00;
            *reinterpret_cast<float2*>(&Sd[i0 * SSTR + 2 * jj0]) = dd;
        }
        if (vj) {
            const int idx = i0 * NTOK + jj1;
            s01 += rpb[rel_idx[idx] * NH + h] + mrow[idx];
            float2 dd; dd.x = s01; dd.y = s01;
            *reinterpret_cast<float2*>(&Sd[i0 * SSTR + 2 * jj1]) = dd;
        }
        if (vi) {
            const int idx = i1 * NTOK + jj0;
            s10 += rpb[rel_idx[idx] * NH + h] + mrow[idx];
            float2 dd; dd.x = s10; dd.y = s10;
            *reinterpret_cast<float2*>(&Sd[i1 * SSTR + 2 * jj0]) = dd;
            if (vj) {
                const int idx1 = i1 * NTOK + jj1;
                s11 += rpb[rel_idx[idx1] * NH + h] + mrow[idx1];
                float2 ee; ee.x = s11; ee.y = s11;
                *reinterpret_cast<float2*>(&Sd[i1 * SSTR + 2 * jj1]) = ee;
            }
        }
    }
    __syncthreads();

    const int lane = tid & 31;
    const int wid  = tid >> 5;
    for (int i = wid; i < NTOK; i += 8) {
        float mval = -3.4e38f;
        for (int j = lane; j < NTOK; j += 32) mval = fmaxf(mval, Sd[i * SSTR + 2 * j]);
#pragma unroll
        for (int o = 16; o > 0; o >>= 1)
            mval = fmaxf(mval, __shfl_xor_sync(0xffffffffu, mval, o));
        float sum = 0.f;
        float ev[2];
        for (int j = lane, c = 0; j < NTOK; j += 32, c++) {
            const float e = expf(Sd[i * SSTR + 2 * j] - mval);
            ev[c] = e;
            sum += e;
        }
#pragma unroll
        for (int o = 16; o > 0; o >>= 1)
            sum += __shfl_xor_sync(0xffffffffu, sum, o);
        const float inv = 1.0f / sum;
        for (int j = lane, c = 0; j < NTOK; j += 32, c++) {
            const float pv = ev[c] * inv;
            float2 dd; dd.x = pv; dd.y = pv;
            *reinterpret_cast<float2*>(&Sd[i * SSTR + 2 * j]) = dd;
            if (attn_out)
                attn_out[(size_t)bh * (NTOK * NTOK) + i * NTOK + j] = pv;
        }
    }
    __syncthreads();

    for (int it = tid; it < 25 * (HD / 2); it += 256) {
        const int ip = it >> 4, dp = it & 15;
        const int i0 = 2 * ip, i1 = i0 + 1;
        const bool vi = (i1 < NTOK);
        u64 c0 = 0, c1 = 0;
#pragma unroll 7
        for (int j = 0; j < NTOK; j++) {
            const u64 vv = *reinterpret_cast<const u64*>(&vs[j * QSTR + 2 * dp]);
            const u64 p0 = *reinterpret_cast<const u64*>(&Sd[i0 * SSTR + 2 * j]);
            ffma2(c0, p0, vv);
            if (vi) {
                const u64 p1 = *reinterpret_cast<const u64*>(&Sd[i1 * SSTR + 2 * j]);
                ffma2(c1, p1, vv);
            }
        }
        const size_t o0 = ((size_t)b * NTOK + i0) * DIMC + h * HD + 2 * dp;
        *reinterpret_cast<float2*>(&g_ctx[o0]) = *reinterpret_cast<float2*>(&c0);
        if (vi) {
            const size_t o1 = ((size_t)b * NTOK + i1) * DIMC + h * HD + 2 * dp;
            *reinterpret_cast<float2*>(&g_ctx[o1]) = *reinterpret_cast<float2*>(&c1);
        }
    }
}

// ---------------------------------------------------------------------------
// Launch
// ---------------------------------------------------------------------------
extern "C" void kernel_launch(void* const* d_in, const int* in_sizes, int n_in,
                              void* d_out, int out_size)
{
    const float* x      = (const float*)d_in[0];
    const float* mask   = (const float*)d_in[1];
    const float* qkv_w  = (const float*)d_in[2];
    const float* qkv_b  = (const float*)d_in[3];
    const float* proj_w = (const float*)d_in[4];
    const float* proj_b = (const float*)d_in[5];
    const float* rpb    = (const float*)d_in[6];
    const int*   relidx = (const int*)d_in[7];

    float* out = (float*)d_out;
    const long OUT_ELEMS  = (long)B_ * NTOK * DIMC;          // 38,535,168
    const long ATTN_ELEMS = (long)B_ * NH * NTOK * NTOK;     // 59,006,976
    float* attn_out = nullptr;
    if ((long)out_size >= OUT_ELEMS + ATTN_ELEMS) attn_out = out + OUT_ELEMS;

    qkv_gemm_kernel<<<dim3(576 / BN, (B_ * NTOK) / BM), 128>>>(x, qkv_w, qkv_b);
    attn_kernel<<<B_ * NH, 256>>>(mask, rpb, relidx, attn_out);
    proj_gemm_kernel<<<dim3(DIMC / BN, (B_ * NTOK) / BM), 128>>>(proj_w, proj_b, out);

    (void)in_sizes; (void)n_in;
}

// round 10
// speedup vs baseline: 3.2747x; 1.0918x over previous
#include <cuda_runtime.h>

#define B_    4096
#define NTOK  49
#define DIMC  192
#define NH    6
#define HD    32
#define NWIN  64

#define BM  128
#define BN  64
#define BKC 16
#define NCH (DIMC / BKC)   // 12 k-chunks
#define AST 24             // u32 stride per SMEM row (conflict-free fragments)

typedef unsigned long long u64;
typedef unsigned int u32;

// Scratch (device globals — allocation-free per harness rules)
__device__ float g_q[(size_t)B_ * NH * NTOK * HD];   // q pre-scaled by hd^-0.5
__device__ float g_k[(size_t)B_ * NH * NTOK * HD];
__device__ float g_v[(size_t)B_ * NH * NTOK * HD];
__device__ float g_ctx[(size_t)B_ * NTOK * DIMC];

#define BMS 52   // bm row stride (float4-aligned blocks of 4)
__device__ float g_bm[(size_t)NWIN * NH * NTOK * BMS];  // rpb-gather + mask, precomputed

__device__ __forceinline__ u32 f2tf(float f) {
    u32 r; asm("cvt.rna.tf32.f32 %0, %1;" : "=r"(r) : "f"(f)); return r;
}
__device__ __forceinline__ void mma_tf32(float* d, u32 a0, u32 a1, u32 a2, u32 a3,
                                         u32 b0, u32 b1) {
    asm volatile(
        "mma.sync.aligned.m16n8k8.row.col.f32.tf32.tf32.f32 "
        "{%0,%1,%2,%3}, {%4,%5,%6,%7}, {%8,%9}, {%0,%1,%2,%3};"
        : "+f"(d[0]), "+f"(d[1]), "+f"(d[2]), "+f"(d[3])
        : "r"(a0), "r"(a1), "r"(a2), "r"(a3), "r"(b0), "r"(b1));
}
__device__ __forceinline__ void ffma2(u64& acc, u64 a, u64 b) {
    asm("fma.rn.f32x2 %0, %1, %2, %0;" : "+l"(acc) : "l"(a), "l"(b));
}

// ===========================================================================
// tf32 MMA GEMM mainloop (unchanged from R9 — working)
// ===========================================================================
#define TF32_GEMM_MAINLOOP(XPTR, WPTR)                                         \
    __shared__ __align__(16) u32 As[2][BM * AST];                              \
    __shared__ __align__(16) u32 Bs[2][BN * AST];                              \
    const int tid   = threadIdx.x;                                             \
    const int lane  = tid & 31;                                                \
    const int wid   = tid >> 5;                                                \
    const int m0    = blockIdx.y * BM;                                         \
    const int j0    = blockIdx.x * BN;                                         \
    const int ldrow = tid >> 2;                                                \
    const int ldcg  = tid & 3;                                                 \
    const int ldoff = (ldcg & 1) + (ldcg >> 1) * 8;                            \
    const int frow  = lane >> 2;                                               \
    const int fcol  = lane & 3;                                                \
    const int wm    = wid * 32;                                                \
    float acc[2][8][4];                                                        \
    _Pragma("unroll") for (int i = 0; i < 2; i++)                              \
        _Pragma("unroll") for (int j = 0; j < 8; j++)                          \
            _Pragma("unroll") for (int e = 0; e < 4; e++) acc[i][j][e] = 0.f;  \
    float4 aR[4]; float4 bR[2];                                                \
    _Pragma("unroll") for (int s = 0; s < 4; s++)                              \
        aR[s] = *reinterpret_cast<const float4*>(                              \
            XPTR + (size_t)(m0 + s * 32 + ldrow) * DIMC + ldcg * 4);           \
    _Pragma("unroll") for (int s = 0; s < 2; s++)                              \
        bR[s] = *reinterpret_cast<const float4*>(                              \
            WPTR + (size_t)(j0 + s * 32 + ldrow) * DIMC + ldcg * 4);           \
    _Pragma("unroll") for (int s = 0; s < 4; s++) {                            \
        const int ba = (s * 32 + ldrow) * AST + ldoff;                         \
        As[0][ba + 0] = f2tf(aR[s].x); As[0][ba + 2] = f2tf(aR[s].y);          \
        As[0][ba + 4] = f2tf(aR[s].z); As[0][ba + 6] = f2tf(aR[s].w);          \
    }                                                                          \
    _Pragma("unroll") for (int s = 0; s < 2; s++) {                            \
        const int ba = (s * 32 + ldrow) * AST + ldoff;                         \
        Bs[0][ba + 0] = f2tf(bR[s].x); Bs[0][ba + 2] = f2tf(bR[s].y);          \
        Bs[0][ba + 4] = f2tf(bR[s].z); Bs[0][ba + 6] = f2tf(bR[s].w);          \
    }                                                                          \
    __syncthreads();                                                           \
    for (int t = 0; t < NCH; t++) {                                            \
        const int buf = t & 1;                                                 \
        if (t + 1 < NCH) {                                                     \
            const int kb = (t + 1) * BKC;                                      \
            _Pragma("unroll") for (int s = 0; s < 4; s++)                      \
                aR[s] = *reinterpret_cast<const float4*>(                      \
                    XPTR + (size_t)(m0 + s * 32 + ldrow) * DIMC + kb + ldcg * 4); \
            _Pragma("unroll") for (int s = 0; s < 2; s++)                      \
                bR[s] = *reinterpret_cast<const float4*>(                      \
                    WPTR + (size_t)(j0 + s * 32 + ldrow) * DIMC + kb + ldcg * 4); \
        }                                                                      \
        _Pragma("unroll") for (int ks = 0; ks < 2; ks++) {                     \
            uint2 afr[2][2];                                                   \
            _Pragma("unroll") for (int am = 0; am < 2; am++) {                 \
                const int r0 = wm + am * 16 + frow;                            \
                afr[am][0] = *reinterpret_cast<const uint2*>(                  \
                    &As[buf][r0 * AST + (ks * 4 + fcol) * 2]);                 \
                afr[am][1] = *reinterpret_cast<const uint2*>(                  \
                    &As[buf][(r0 + 8) * AST + (ks * 4 + fcol) * 2]);           \
            }                                                                  \
            uint2 bfr[8];                                                      \
            _Pragma("unroll") for (int an = 0; an < 8; an++)                   \
                bfr[an] = *reinterpret_cast<const uint2*>(                     \
                    &Bs[buf][(an * 8 + frow) * AST + (ks * 4 + fcol) * 2]);    \
            _Pragma("unroll") for (int am = 0; am < 2; am++)                   \
                _Pragma("unroll") for (int an = 0; an < 8; an++)               \
                    mma_tf32(acc[am][an],                                      \
                             afr[am][0].x, afr[am][1].x,                       \
                             afr[am][0].y, afr[am][1].y,                       \
                             bfr[an].x, bfr[an].y);                            \
        }                                                                      \
        if (t + 1 < NCH) {                                                     \
            const int nb = (t + 1) & 1;                                        \
            _Pragma("unroll") for (int s = 0; s < 4; s++) {                    \
                const int ba = (s * 32 + ldrow) * AST + ldoff;                 \
                As[nb][ba + 0] = f2tf(aR[s].x); As[nb][ba + 2] = f2tf(aR[s].y); \
                As[nb][ba + 4] = f2tf(aR[s].z); As[nb][ba + 6] = f2tf(aR[s].w); \
            }                                                                  \
            _Pragma("unroll") for (int s = 0; s < 2; s++) {                    \
                const int ba = (s * 32 + ldrow) * AST + ldoff;                 \
                Bs[nb][ba + 0] = f2tf(bR[s].x); Bs[nb][ba + 2] = f2tf(bR[s].y); \
                Bs[nb][ba + 4] = f2tf(bR[s].z); Bs[nb][ba + 6] = f2tf(bR[s].w); \
            }                                                                  \
            __syncthreads();                                                   \
        }                                                                      \
    }

// ---------------------------------------------------------------------------
// Kernel 0: precompute bias+mask table  bm[w][h][i][j] = rpb[rel_idx[i,j]][h] + mask[w][i][j]
// ---------------------------------------------------------------------------
__global__ __launch_bounds__(256)
void bias_kernel(const float* __restrict__ mask,
                 const float* __restrict__ rpb,
                 const int*   __restrict__ rel_idx)
{
    const int wh = blockIdx.x;
    const int w  = wh / NH;
    const int h  = wh - w * NH;
    float* dst = g_bm + (size_t)wh * (NTOK * BMS);
    const float* msk = mask + (size_t)w * (NTOK * NTOK);
    for (int idx = threadIdx.x; idx < NTOK * NTOK; idx += 256) {
        const int i = idx / NTOK;
        const int j = idx - i * NTOK;
        dst[i * BMS + j] = rpb[rel_idx[idx] * NH + h] + msk[idx];
    }
}

// ---------------------------------------------------------------------------
// Kernel 1: QKV GEMM + bias, scatter into g_q/g_k/g_v [B,H,N,hd], q *= scale
// ---------------------------------------------------------------------------
__global__ __launch_bounds__(128, 3)
void qkv_gemm_kernel(const float* __restrict__ X,
                     const float* __restrict__ W,
                     const float* __restrict__ bias)
{
    TF32_GEMM_MAINLOOP(X, W)

    const int tt = j0 / DIMC;
    const int r0 = j0 - tt * DIMC;
    float* dstArr = (tt == 0) ? g_q : ((tt == 1) ? g_k : g_v);
    const float mul = (tt == 0) ? 0.17677669529663687f : 1.0f;

#pragma unroll
    for (int an = 0; an < 8; an++) {
        const int jc = an * 8 + fcol * 2;
        const float bx = bias[j0 + jc];
        const float by = bias[j0 + jc + 1];
        const int c = r0 + jc;
        const int h = c >> 5;
        const int d = c & 31;
#pragma unroll
        for (int am = 0; am < 2; am++) {
#pragma unroll
            for (int rh = 0; rh < 2; rh++) {
                const int m  = m0 + wm + am * 16 + frow + rh * 8;
                const int bi = m / NTOK;
                const int ni = m - bi * NTOK;
                const size_t dst = ((size_t)(bi * NH + h) * NTOK + ni) * HD + d;
                float2 o;
                o.x = (acc[am][an][rh * 2 + 0] + bx) * mul;
                o.y = (acc[am][an][rh * 2 + 1] + by) * mul;
                *reinterpret_cast<float2*>(&dstArr[dst]) = o;
            }
        }
    }
}

// ---------------------------------------------------------------------------
// Kernel 3: output projection  out = ctx @ proj_w.T + proj_b
// ---------------------------------------------------------------------------
__global__ __launch_bounds__(128, 3)
void proj_gemm_kernel(const float* __restrict__ W,
                      const float* __restrict__ bias,
                      float* __restrict__ out)
{
    const float* Xg = g_ctx;
    TF32_GEMM_MAINLOOP(Xg, W)

#pragma unroll
    for (int an = 0; an < 8; an++) {
        const int jc = an * 8 + fcol * 2;
        const float bx = bias[j0 + jc];
        const float by = bias[j0 + jc + 1];
#pragma unroll
        for (int am = 0; am < 2; am++) {
#pragma unroll
            for (int rh = 0; rh < 2; rh++) {
                const int m = m0 + wm + am * 16 + frow + rh * 8;
                float2 o;
                o.x = acc[am][an][rh * 2 + 0] + bx;
                o.y = acc[am][an][rh * 2 + 1] + by;
                *reinterpret_cast<float2*>(&out[(size_t)m * DIMC + j0 + jc]) = o;
            }
        }
    }
}

// ---------------------------------------------------------------------------
// Kernel 2: per-(window, head) attention, fp32 (f32x2), 4x4 / 4-row blocking.
// ---------------------------------------------------------------------------
#define QSTR 34
#define SSTR 100

__global__ __launch_bounds__(256)
void attn_kernel(float* __restrict__ attn_out)
{
    __shared__ float qs[NTOK * QSTR];
    __shared__ float ks[NTOK * QSTR];
    __shared__ float vs[NTOK * QSTR];
    __shared__ float Sd[NTOK * SSTR];   // duplicated pairs: Sd[i*100+2j]==[..+1]

    const int bh  = blockIdx.x;
    const int b   = bh / NH;
    const int h   = bh - b * NH;
    const int tid = threadIdx.x;

    // ---- stage q/k/v as float2 ----
    const size_t base2 = (size_t)bh * (NTOK * HD / 2);
    const float2* q2 = reinterpret_cast<const float2*>(g_q) + base2;
    const float2* k2 = reinterpret_cast<const float2*>(g_k) + base2;
    const float2* v2 = reinterpret_cast<const float2*>(g_v) + base2;
    for (int idx = tid; idx < NTOK * (HD / 2); idx += 256) {
        const int r = idx >> 4, dp = idx & 15;
        *reinterpret_cast<float2*>(&qs[r * QSTR + 2 * dp]) = q2[idx];
        *reinterpret_cast<float2*>(&ks[r * QSTR + 2 * dp]) = k2[idx];
        *reinterpret_cast<float2*>(&vs[r * QSTR + 2 * dp]) = v2[idx];
    }
    __syncthreads();

    // ---- S = q k^T + bm : 4x4 register-blocked, one task per thread ----
    const float* bm = g_bm + (size_t)((b & (NWIN - 1)) * NH + h) * (NTOK * BMS);
    if (tid < 13 * 13) {
        const int bi = tid / 13, bj = tid - 13 * (tid / 13);
        const int i0 = bi * 4, j0 = bj * 4;
        const u64* qp[4]; const u64* kp[4];
#pragma unroll
        for (int t = 0; t < 4; t++) {
            const int ri = (i0 + t < NTOK) ? (i0 + t) : (NTOK - 1);
            const int rj = (j0 + t < NTOK) ? (j0 + t) : (NTOK - 1);
            qp[t] = reinterpret_cast<const u64*>(&qs[ri * QSTR]);
            kp[t] = reinterpret_cast<const u64*>(&ks[rj * QSTR]);
        }
        u64 acc[4][4];
#pragma unroll
        for (int a = 0; a < 4; a++)
#pragma unroll
            for (int c = 0; c < 4; c++) acc[a][c] = 0ull;
#pragma unroll
        for (int d = 0; d < HD / 2; d++) {
            u64 qv[4], kv[4];
#pragma unroll
            for (int t = 0; t < 4; t++) { qv[t] = qp[t][d]; kv[t] = kp[t][d]; }
#pragma unroll
            for (int a = 0; a < 4; a++)
#pragma unroll
                for (int c = 0; c < 4; c++)
                    ffma2(acc[a][c], qv[a], kv[c]);
        }
#pragma unroll
        for (int a = 0; a < 4; a++) {
            const int i = i0 + a;
            if (i < NTOK) {
                const float4 bmv = *reinterpret_cast<const float4*>(&bm[i * BMS + j0]);
                const float bb[4] = {bmv.x, bmv.y, bmv.z, bmv.w};
#pragma unroll
                for (int c = 0; c < 4; c++) {
                    if (j0 + c < NTOK) {
                        float2 f = *reinterpret_cast<float2*>(&acc[a][c]);
                        const float s = f.x + f.y + bb[c];
                        float2 dd; dd.x = s; dd.y = s;
                        *reinterpret_cast<float2*>(&Sd[i * SSTR + 2 * (j0 + c)]) = dd;
                    }
                }
            }
        }
    }
    __syncthreads();

    // ---- row softmax (warp per row, 8 warps striding), write attn ----
    const int lane = tid & 31;
    const int wid  = tid >> 5;
    for (int i = wid; i < NTOK; i += 8) {
        float mval = -3.4e38f;
        for (int j = lane; j < NTOK; j += 32) mval = fmaxf(mval, Sd[i * SSTR + 2 * j]);
#pragma unroll
        for (int o = 16; o > 0; o >>= 1)
            mval = fmaxf(mval, __shfl_xor_sync(0xffffffffu, mval, o));
        float sum = 0.f;
        float ev[2];
        for (int j = lane, c = 0; j < NTOK; j += 32, c++) {
            const float e = __expf(Sd[i * SSTR + 2 * j] - mval);
            ev[c] = e;
            sum += e;
        }
#pragma unroll
        for (int o = 16; o > 0; o >>= 1)
            sum += __shfl_xor_sync(0xffffffffu, sum, o);
        const float inv = 1.0f / sum;
        for (int j = lane, c = 0; j < NTOK; j += 32, c++) {
            const float pv = ev[c] * inv;
            float2 dd; dd.x = pv; dd.y = pv;
            *reinterpret_cast<float2*>(&Sd[i * SSTR + 2 * j]) = dd;
            if (attn_out)
                attn_out[(size_t)bh * (NTOK * NTOK) + i * NTOK + j] = pv;
        }
    }
    __syncthreads();

    // ---- ctx = P V : 4 rows x 1 d-pair per thread (13*16 = 208 tasks) ----
    if (tid < 13 * 16) {
        const int bi = tid >> 4, dp = tid & 15;
        const int i0 = bi * 4;
        const int r1 = (i0 + 1 < NTOK) ? i0 + 1 : NTOK - 1;
        const int r2 = (i0 + 2 < NTOK) ? i0 + 2 : NTOK - 1;
        const int r3 = (i0 + 3 < NTOK) ? i0 + 3 : NTOK - 1;
        u64 c0 = 0, c1 = 0, c2 = 0, c3 = 0;
#pragma unroll 7
        for (int j = 0; j < NTOK; j++) {
            const u64 vv = *reinterpret_cast<const u64*>(&vs[j * QSTR + 2 * dp]);
            ffma2(c0, *reinterpret_cast<const u64*>(&Sd[i0 * SSTR + 2 * j]), vv);
            ffma2(c1, *reinterpret_cast<const u64*>(&Sd[r1 * SSTR + 2 * j]), vv);
            ffma2(c2, *reinterpret_cast<const u64*>(&Sd[r2 * SSTR + 2 * j]), vv);
            ffma2(c3, *reinterpret_cast<const u64*>(&Sd[r3 * SSTR + 2 * j]), vv);
        }
        const size_t ob = (size_t)b * NTOK * DIMC + h * HD + 2 * dp;
        *reinterpret_cast<float2*>(&g_ctx[ob + (size_t)i0 * DIMC]) = *reinterpret_cast<float2*>(&c0);
        if (i0 + 1 < NTOK) *reinterpret_cast<float2*>(&g_ctx[ob + (size_t)(i0 + 1) * DIMC]) = *reinterpret_cast<float2*>(&c1);
        if (i0 + 2 < NTOK) *reinterpret_cast<float2*>(&g_ctx[ob + (size_t)(i0 + 2) * DIMC]) = *reinterpret_cast<float2*>(&c2);
        if (i0 + 3 < NTOK) *reinterpret_cast<float2*>(&g_ctx[ob + (size_t)(i0 + 3) * DIMC]) = *reinterpret_cast<float2*>(&c3);
    }
}

// ---------------------------------------------------------------------------
// Launch
// ---------------------------------------------------------------------------
extern "C" void kernel_launch(void* const* d_in, const int* in_sizes, int n_in,
                              void* d_out, int out_size)
{
    const float* x      = (const float*)d_in[0];
    const float* mask   = (const float*)d_in[1];
    const float* qkv_w  = (const float*)d_in[2];
    const float* qkv_b  = (const float*)d_in[3];
    const float* proj_w = (const float*)d_in[4];
    const float* proj_b = (const float*)d_in[5];
    const float* rpb    = (const float*)d_in[6];
    const int*   relidx = (const int*)d_in[7];

    float* out = (float*)d_out;
    const long OUT_ELEMS  = (long)B_ * NTOK * DIMC;          // 38,535,168
    const long ATTN_ELEMS = (long)B_ * NH * NTOK * NTOK;     // 59,006,976
    float* attn_out = nullptr;
    if ((long)out_size >= OUT_ELEMS + ATTN_ELEMS) attn_out = out + OUT_ELEMS;

    bias_kernel<<<NWIN * NH, 256>>>(mask, rpb, relidx);
    qkv_gemm_kernel<<<dim3(576 / BN, (B_ * NTOK) / BM), 128>>>(x, qkv_w, qkv_b);
    attn_kernel<<<B_ * NH, 256>>>(attn_out);
    proj_gemm_kernel<<<dim3(DIMC / BN, (B_ * NTOK) / BM), 128>>>(proj_w, proj_b, out);

    (void)in_sizes; (void)n_in;
}

// round 11
// speedup vs baseline: 3.2799x; 1.0016x over previous
#include <cuda_runtime.h>

#define B_    4096
#define NTOK  49
#define DIMC  192
#define NH    6
#define HD    32
#define NWIN  64

#define BM  128
#define BN  64
#define BKC 16
#define NCH (DIMC / BKC)   // 12 k-chunks
#define AST 24             // u32 stride per SMEM row (conflict-free fragments)

typedef unsigned long long u64;
typedef unsigned int u32;

// Scratch (device globals — allocation-free per harness rules)
__device__ float g_q[(size_t)B_ * NH * NTOK * HD];   // q pre-scaled by hd^-0.5
__device__ float g_k[(size_t)B_ * NH * NTOK * HD];
__device__ float g_v[(size_t)B_ * NH * NTOK * HD];
__device__ float g_ctx[(size_t)B_ * NTOK * DIMC];

#define BMS 52   // bm row stride (float4-aligned blocks of 4)
__device__ float g_bm[(size_t)NWIN * NH * NTOK * BMS];  // rpb-gather + mask, precomputed

__device__ __forceinline__ u32 f2tf(float f) {
    u32 r; asm("cvt.rna.tf32.f32 %0, %1;" : "=r"(r) : "f"(f)); return r;
}
__device__ __forceinline__ void mma_tf32(float* d, u32 a0, u32 a1, u32 a2, u32 a3,
                                         u32 b0, u32 b1) {
    asm volatile(
        "mma.sync.aligned.m16n8k8.row.col.f32.tf32.tf32.f32 "
        "{%0,%1,%2,%3}, {%4,%5,%6,%7}, {%8,%9}, {%0,%1,%2,%3};"
        : "+f"(d[0]), "+f"(d[1]), "+f"(d[2]), "+f"(d[3])
        : "r"(a0), "r"(a1), "r"(a2), "r"(a3), "r"(b0), "r"(b1));
}
__device__ __forceinline__ void ffma2(u64& acc, u64 a, u64 b) {
    asm("fma.rn.f32x2 %0, %1, %2, %0;" : "+l"(acc) : "l"(a), "l"(b));
}

// ===========================================================================
// tf32 MMA GEMM mainloop (unchanged from R9 — working)
// ===========================================================================
#define TF32_GEMM_MAINLOOP(XPTR, WPTR)                                         \
    __shared__ __align__(16) u32 As[2][BM * AST];                              \
    __shared__ __align__(16) u32 Bs[2][BN * AST];                              \
    const int tid   = threadIdx.x;                                             \
    const int lane  = tid & 31;                                                \
    const int wid   = tid >> 5;                                                \
    const int m0    = blockIdx.y * BM;                                         \
    const int j0    = blockIdx.x * BN;                                         \
    const int ldrow = tid >> 2;                                                \
    const int ldcg  = tid & 3;                                                 \
    const int ldoff = (ldcg & 1) + (ldcg >> 1) * 8;                            \
    const int frow  = lane >> 2;                                               \
    const int fcol  = lane & 3;                                                \
    const int wm    = wid * 32;                                                \
    float acc[2][8][4];                                                        \
    _Pragma("unroll") for (int i = 0; i < 2; i++)                              \
        _Pragma("unroll") for (int j = 0; j < 8; j++)                          \
            _Pragma("unroll") for (int e = 0; e < 4; e++) acc[i][j][e] = 0.f;  \
    float4 aR[4]; float4 bR[2];                                                \
    _Pragma("unroll") for (int s = 0; s < 4; s++)                              \
        aR[s] = *reinterpret_cast<const float4*>(                              \
            XPTR + (size_t)(m0 + s * 32 + ldrow) * DIMC + ldcg * 4);           \
    _Pragma("unroll") for (int s = 0; s < 2; s++)                              \
        bR[s] = *reinterpret_cast<const float4*>(                              \
            WPTR + (size_t)(j0 + s * 32 + ldrow) * DIMC + ldcg * 4);           \
    _Pragma("unroll") for (int s = 0; s < 4; s++) {                            \
        const int ba = (s * 32 + ldrow) * AST + ldoff;                         \
        As[0][ba + 0] = f2tf(aR[s].x); As[0][ba + 2] = f2tf(aR[s].y);          \
        As[0][ba + 4] = f2tf(aR[s].z); As[0][ba + 6] = f2tf(aR[s].w);          \
    }                                                                          \
    _Pragma("unroll") for (int s = 0; s < 2; s++) {                            \
        const int ba = (s * 32 + ldrow) * AST + ldoff;                         \
        Bs[0][ba + 0] = f2tf(bR[s].x); Bs[0][ba + 2] = f2tf(bR[s].y);          \
        Bs[0][ba + 4] = f2tf(bR[s].z); Bs[0][ba + 6] = f2tf(bR[s].w);          \
    }                                                                          \
    __syncthreads();                                                           \
    for (int t = 0; t < NCH; t++) {                                            \
        const int buf = t & 1;                                                 \
        if (t + 1 < NCH) {                                                     \
            const int kb = (t + 1) * BKC;                                      \
            _Pragma("unroll") for (int s = 0; s < 4; s++)                      \
                aR[s] = *reinterpret_cast<const float4*>(                      \
                    XPTR + (size_t)(m0 + s * 32 + ldrow) * DIMC + kb + ldcg * 4); \
            _Pragma("unroll") for (int s = 0; s < 2; s++)                      \
                bR[s] = *reinterpret_cast<const float4*>(                      \
                    WPTR + (size_t)(j0 + s * 32 + ldrow) * DIMC + kb + ldcg * 4); \
        }                                                                      \
        _Pragma("unroll") for (int ks = 0; ks < 2; ks++) {                     \
            uint2 afr[2][2];                                                   \
            _Pragma("unroll") for (int am = 0; am < 2; am++) {                 \
                const int r0 = wm + am * 16 + frow;                            \
                afr[am][0] = *reinterpret_cast<const uint2*>(                  \
                    &As[buf][r0 * AST + (ks * 4 + fcol) * 2]);                 \
                afr[am][1] = *reinterpret_cast<const uint2*>(                  \
                    &As[buf][(r0 + 8) * AST + (ks * 4 + fcol) * 2]);           \
            }                                                                  \
            uint2 bfr[8];                                                      \
            _Pragma("unroll") for (int an = 0; an < 8; an++)                   \
                bfr[an] = *reinterpret_cast<const uint2*>(                     \
                    &Bs[buf][(an * 8 + frow) * AST + (ks * 4 + fcol) * 2]);    \
            _Pragma("unroll") for (int am = 0; am < 2; am++)                   \
                _Pragma("unroll") for (int an = 0; an < 8; an++)               \
                    mma_tf32(acc[am][an],                                      \
                             afr[am][0].x, afr[am][1].x,                       \
                             afr[am][0].y, afr[am][1].y,                       \
                             bfr[an].x, bfr[an].y);                            \
        }                                                                      \
        if (t + 1 < NCH) {                                                     \
            const int nb = (t + 1) & 1;                                        \
            _Pragma("unroll") for (int s = 0; s < 4; s++) {                    \
                const int ba = (s * 32 + ldrow) * AST + ldoff;                 \
                As[nb][ba + 0] = f2tf(aR[s].x); As[nb][ba + 2] = f2tf(aR[s].y); \
                As[nb][ba + 4] = f2tf(aR[s].z); As[nb][ba + 6] = f2tf(aR[s].w); \
            }                                                                  \
            _Pragma("unroll") for (int s = 0; s < 2; s++) {                    \
                const int ba = (s * 32 + ldrow) * AST + ldoff;                 \
                Bs[nb][ba + 0] = f2tf(bR[s].x); Bs[nb][ba + 2] = f2tf(bR[s].y); \
                Bs[nb][ba + 4] = f2tf(bR[s].z); Bs[nb][ba + 6] = f2tf(bR[s].w); \
            }                                                                  \
            __syncthreads();                                                   \
        }                                                                      \
    }

// ---------------------------------------------------------------------------
// Kernel 0: precompute bias+mask table  bm[w][h][i][j] = rpb[rel_idx[i,j]][h] + mask[w][i][j]
// ---------------------------------------------------------------------------
__global__ __launch_bounds__(256)
void bias_kernel(const float* __restrict__ mask,
                 const float* __restrict__ rpb,
                 const int*   __restrict__ rel_idx)
{
    const int wh = blockIdx.x;
    const int w  = wh / NH;
    const int h  = wh - w * NH;
    float* dst = g_bm + (size_t)wh * (NTOK * BMS);
    const float* msk = mask + (size_t)w * (NTOK * NTOK);
    for (int idx = threadIdx.x; idx < NTOK * NTOK; idx += 256) {
        const int i = idx / NTOK;
        const int j = idx - i * NTOK;
        dst[i * BMS + j] = rpb[rel_idx[idx] * NH + h] + msk[idx];
    }
}

// ---------------------------------------------------------------------------
// Kernel 1: QKV GEMM + bias, scatter into g_q/g_k/g_v [B,H,N,hd], q *= scale
// ---------------------------------------------------------------------------
__global__ __launch_bounds__(128, 3)
void qkv_gemm_kernel(const float* __restrict__ X,
                     const float* __restrict__ W,
                     const float* __restrict__ bias)
{
    TF32_GEMM_MAINLOOP(X, W)

    const int tt = j0 / DIMC;
    const int r0 = j0 - tt * DIMC;
    float* dstArr = (tt == 0) ? g_q : ((tt == 1) ? g_k : g_v);
    const float mul = (tt == 0) ? 0.17677669529663687f : 1.0f;

#pragma unroll
    for (int an = 0; an < 8; an++) {
        const int jc = an * 8 + fcol * 2;
        const float bx = bias[j0 + jc];
        const float by = bias[j0 + jc + 1];
        const int c = r0 + jc;
        const int h = c >> 5;
        const int d = c & 31;
#pragma unroll
        for (int am = 0; am < 2; am++) {
#pragma unroll
            for (int rh = 0; rh < 2; rh++) {
                const int m  = m0 + wm + am * 16 + frow + rh * 8;
                const int bi = m / NTOK;
                const int ni = m - bi * NTOK;
                const size_t dst = ((size_t)(bi * NH + h) * NTOK + ni) * HD + d;
                float2 o;
                o.x = (acc[am][an][rh * 2 + 0] + bx) * mul;
                o.y = (acc[am][an][rh * 2 + 1] + by) * mul;
                *reinterpret_cast<float2*>(&dstArr[dst]) = o;
            }
        }
    }
}

// ---------------------------------------------------------------------------
// Kernel 3: output projection  out = ctx @ proj_w.T + proj_b
// ---------------------------------------------------------------------------
__global__ __launch_bounds__(128, 3)
void proj_gemm_kernel(const float* __restrict__ W,
                      const float* __restrict__ bias,
                      float* __restrict__ out)
{
    const float* Xg = g_ctx;
    TF32_GEMM_MAINLOOP(Xg, W)

#pragma unroll
    for (int an = 0; an < 8; an++) {
        const int jc = an * 8 + fcol * 2;
        const float bx = bias[j0 + jc];
        const float by = bias[j0 + jc + 1];
#pragma unroll
        for (int am = 0; am < 2; am++) {
#pragma unroll
            for (int rh = 0; rh < 2; rh++) {
                const int m = m0 + wm + am * 16 + frow + rh * 8;
                float2 o;
                o.x = acc[am][an][rh * 2 + 0] + bx;
                o.y = acc[am][an][rh * 2 + 1] + by;
                *reinterpret_cast<float2*>(&out[(size_t)m * DIMC + j0 + jc]) = o;
            }
        }
    }
}

// ---------------------------------------------------------------------------
// Kernel 2: per-(window, head) attention, fp32 (f32x2), 4x4 / 4-row blocking.
// ---------------------------------------------------------------------------
#define QSTR 34
#define SSTR 100

__global__ __launch_bounds__(256)
void attn_kernel(float* __restrict__ attn_out)
{
    __shared__ float qs[NTOK * QSTR];
    __shared__ float ks[NTOK * QSTR];
    __shared__ float vs[NTOK * QSTR];
    __shared__ float Sd[NTOK * SSTR];   // duplicated pairs: Sd[i*100+2j]==[..+1]

    const int bh  = blockIdx.x;
    const int b   = bh / NH;
    const int h   = bh - b * NH;
    const int tid = threadIdx.x;

    // ---- stage q/k/v as float2 ----
    const size_t base2 = (size_t)bh * (NTOK * HD / 2);
    const float2* q2 = reinterpret_cast<const float2*>(g_q) + base2;
    const float2* k2 = reinterpret_cast<const float2*>(g_k) + base2;
    const float2* v2 = reinterpret_cast<const float2*>(g_v) + base2;
    for (int idx = tid; idx < NTOK * (HD / 2); idx += 256) {
        const int r = idx >> 4, dp = idx & 15;
        *reinterpret_cast<float2*>(&qs[r * QSTR + 2 * dp]) = q2[idx];
        *reinterpret_cast<float2*>(&ks[r * QSTR + 2 * dp]) = k2[idx];
        *reinterpret_cast<float2*>(&vs[r * QSTR + 2 * dp]) = v2[idx];
    }
    __syncthreads();

    // ---- S = q k^T + bm : 4x4 register-blocked, one task per thread ----
    const float* bm = g_bm + (size_t)((b & (NWIN - 1)) * NH + h) * (NTOK * BMS);
    if (tid < 13 * 13) {
        const int bi = tid / 13, bj = tid - 13 * (tid / 13);
        const int i0 = bi * 4, j0 = bj * 4;
        const u64* qp[4]; const u64* kp[4];
#pragma unroll
        for (int t = 0; t < 4; t++) {
            const int ri = (i0 + t < NTOK) ? (i0 + t) : (NTOK - 1);
            const int rj = (j0 + t < NTOK) ? (j0 + t) : (NTOK - 1);
            qp[t] = reinterpret_cast<const u64*>(&qs[ri * QSTR]);
            kp[t] = reinterpret_cast<const u64*>(&ks[rj * QSTR]);
        }
        u64 acc[4][4];
#pragma unroll
        for (int a = 0; a < 4; a++)
#pragma unroll
            for (int c = 0; c < 4; c++) acc[a][c] = 0ull;
#pragma unroll
        for (int d = 0; d < HD / 2; d++) {
            u64 qv[4], kv[4];
#pragma unroll
            for (int t = 0; t < 4; t++) { qv[t] = qp[t][d]; kv[t] = kp[t][d]; }
#pragma unroll
            for (int a = 0; a < 4; a++)
#pragma unroll
                for (int c = 0; c < 4; c++)
                    ffma2(acc[a][c], qv[a], kv[c]);
        }
#pragma unroll
        for (int a = 0; a < 4; a++) {
            const int i = i0 + a;
            if (i < NTOK) {
                const float4 bmv = *reinterpret_cast<const float4*>(&bm[i * BMS + j0]);
                const float bb[4] = {bmv.x, bmv.y, bmv.z, bmv.w};
#pragma unroll
                for (int c = 0; c < 4; c++) {
                    if (j0 + c < NTOK) {
                        float2 f = *reinterpret_cast<float2*>(&acc[a][c]);
                        const float s = f.x + f.y + bb[c];
                        float2 dd; dd.x = s; dd.y = s;
                        *reinterpret_cast<float2*>(&Sd[i * SSTR + 2 * (j0 + c)]) = dd;
                    }
                }
            }
        }
    }
    __syncthreads();

    // ---- row softmax (warp per row, 8 warps striding), write attn ----
    const int lane = tid & 31;
    const int wid  = tid >> 5;
    for (int i = wid; i < NTOK; i += 8) {
        float mval = -3.4e38f;
        for (int j = lane; j < NTOK; j += 32) mval = fmaxf(mval, Sd[i * SSTR + 2 * j]);
#pragma unroll
        for (int o = 16; o > 0; o >>= 1)
            mval = fmaxf(mval, __shfl_xor_sync(0xffffffffu, mval, o));
        float sum = 0.f;
        float ev[2];
        for (int j = lane, c = 0; j < NTOK; j += 32, c++) {
            const float e = __expf(Sd[i * SSTR + 2 * j] - mval);
            ev[c] = e;
            sum += e;
        }
#pragma unroll
        for (int o = 16; o > 0; o >>= 1)
            sum += __shfl_xor_sync(0xffffffffu, sum, o);
        const float inv = 1.0f / sum;
        for (int j = lane, c = 0; j < NTOK; j += 32, c++) {
            const float pv = ev[c] * inv;
            float2 dd; dd.x = pv; dd.y = pv;
            *reinterpret_cast<float2*>(&Sd[i * SSTR + 2 * j]) = dd;
            if (attn_out)
                attn_out[(size_t)bh * (NTOK * NTOK) + i * NTOK + j] = pv;
        }
    }
    __syncthreads();

    // ---- ctx = P V : 4 rows x 1 d-pair per thread (13*16 = 208 tasks) ----
    if (tid < 13 * 16) {
        const int bi = tid >> 4, dp = tid & 15;
        const int i0 = bi * 4;
        const int r1 = (i0 + 1 < NTOK) ? i0 + 1 : NTOK - 1;
        const int r2 = (i0 + 2 < NTOK) ? i0 + 2 : NTOK - 1;
        const int r3 = (i0 + 3 < NTOK) ? i0 + 3 : NTOK - 1;
        u64 c0 = 0, c1 = 0, c2 = 0, c3 = 0;
#pragma unroll 7
        for (int j = 0; j < NTOK; j++) {
            const u64 vv = *reinterpret_cast<const u64*>(&vs[j * QSTR + 2 * dp]);
            ffma2(c0, *reinterpret_cast<const u64*>(&Sd[i0 * SSTR + 2 * j]), vv);
            ffma2(c1, *reinterpret_cast<const u64*>(&Sd[r1 * SSTR + 2 * j]), vv);
            ffma2(c2, *reinterpret_cast<const u64*>(&Sd[r2 * SSTR + 2 * j]), vv);
            ffma2(c3, *reinterpret_cast<const u64*>(&Sd[r3 * SSTR + 2 * j]), vv);
        }
        const size_t ob = (size_t)b * NTOK * DIMC + h * HD + 2 * dp;
        *reinterpret_cast<float2*>(&g_ctx[ob + (size_t)i0 * DIMC]) = *reinterpret_cast<float2*>(&c0);
        if (i0 + 1 < NTOK) *reinterpret_cast<float2*>(&g_ctx[ob + (size_t)(i0 + 1) * DIMC]) = *reinterpret_cast<float2*>(&c1);
        if (i0 + 2 < NTOK) *reinterpret_cast<float2*>(&g_ctx[ob + (size_t)(i0 + 2) * DIMC]) = *reinterpret_cast<float2*>(&c2);
        if (i0 + 3 < NTOK) *reinterpret_cast<float2*>(&g_ctx[ob + (size_t)(i0 + 3) * DIMC]) = *reinterpret_cast<float2*>(&c3);
    }
}

// ---------------------------------------------------------------------------
// Launch
// ---------------------------------------------------------------------------
extern "C" void kernel_launch(void* const* d_in, const int* in_sizes, int n_in,
                              void* d_out, int out_size)
{
    const float* x      = (const float*)d_in[0];
    const float* mask   = (const float*)d_in[1];
    const float* qkv_w  = (const float*)d_in[2];
    const float* qkv_b  = (const float*)d_in[3];
    const float* proj_w = (const float*)d_in[4];
    const float* proj_b = (const float*)d_in[5];
    const float* rpb    = (const float*)d_in[6];
    const int*   relidx = (const int*)d_in[7];

    float* out = (float*)d_out;
    const long OUT_ELEMS  = (long)B_ * NTOK * DIMC;          // 38,535,168
    const long ATTN_ELEMS = (long)B_ * NH * NTOK * NTOK;     // 59,006,976
    float* attn_out = nullptr;
    if ((long)out_size >= OUT_ELEMS + ATTN_ELEMS) attn_out = out + OUT_ELEMS;

    bias_kernel<<<NWIN * NH, 256>>>(mask, rpb, relidx);
    qkv_gemm_kernel<<<dim3(576 / BN, (B_ * NTOK) / BM), 128>>>(x, qkv_w, qkv_b);
    attn_kernel<<<B_ * NH, 256>>>(attn_out);
    proj_gemm_kernel<<<dim3(DIMC / BN, (B_ * NTOK) / BM), 128>>>(proj_w, proj_b, out);

    (void)in_sizes; (void)n_in;
}

// round 12
// speedup vs baseline: 3.2862x; 1.0019x over previous
#include <cuda_runtime.h>

#define B_    4096
#define NTOK  49
#define DIMC  192
#define NH    6
#define HD    32
#define NWIN  64

#define BM  128
#define BN  64
#define BKC 16
#define NCH (DIMC / BKC)   // 12 k-chunks
#define AST 24             // u32 stride per SMEM row (conflict-free fragments)

typedef unsigned long long u64;
typedef unsigned int u32;

// Scratch (device globals — allocation-free per harness rules)
__device__ float g_q[(size_t)B_ * NH * NTOK * HD];   // q pre-scaled by hd^-0.5
__device__ float g_k[(size_t)B_ * NH * NTOK * HD];
__device__ float g_v[(size_t)B_ * NH * NTOK * HD];
__device__ float g_ctx[(size_t)B_ * NTOK * DIMC];

#define BMS 52   // bm row stride (float4-aligned blocks of 4)
__device__ float g_bm[(size_t)NWIN * NH * NTOK * BMS];  // rpb-gather + mask, precomputed

__device__ __forceinline__ u32 f2tf(float f) {
    u32 r; asm("cvt.rna.tf32.f32 %0, %1;" : "=r"(r) : "f"(f)); return r;
}
__device__ __forceinline__ void mma_tf32(float* d, u32 a0, u32 a1, u32 a2, u32 a3,
                                         u32 b0, u32 b1) {
    asm volatile(
        "mma.sync.aligned.m16n8k8.row.col.f32.tf32.tf32.f32 "
        "{%0,%1,%2,%3}, {%4,%5,%6,%7}, {%8,%9}, {%0,%1,%2,%3};"
        : "+f"(d[0]), "+f"(d[1]), "+f"(d[2]), "+f"(d[3])
        : "r"(a0), "r"(a1), "r"(a2), "r"(a3), "r"(b0), "r"(b1));
}
__device__ __forceinline__ void ffma2(u64& acc, u64 a, u64 b) {
    asm("fma.rn.f32x2 %0, %1, %2, %0;" : "+l"(acc) : "l"(a), "l"(b));
}

// ===========================================================================
// tf32 MMA GEMM mainloop (unchanged — working)
// ===========================================================================
#define TF32_GEMM_MAINLOOP(XPTR, WPTR)                                         \
    __shared__ __align__(16) u32 As[2][BM * AST];                              \
    __shared__ __align__(16) u32 Bs[2][BN * AST];                              \
    const int tid   = threadIdx.x;                                             \
    const int lane  = tid & 31;                                                \
    const int wid   = tid >> 5;                                                \
    const int m0    = blockIdx.y * BM;                                         \
    const int j0    = blockIdx.x * BN;                                         \
    const int ldrow = tid >> 2;                                                \
    const int ldcg  = tid & 3;                                                 \
    const int ldoff = (ldcg & 1) + (ldcg >> 1) * 8;                            \
    const int frow  = lane >> 2;                                               \
    const int fcol  = lane & 3;                                                \
    const int wm    = wid * 32;                                                \
    float acc[2][8][4];                                                        \
    _Pragma("unroll") for (int i = 0; i < 2; i++)                              \
        _Pragma("unroll") for (int j = 0; j < 8; j++)                          \
            _Pragma("unroll") for (int e = 0; e < 4; e++) acc[i][j][e] = 0.f;  \
    float4 aR[4]; float4 bR[2];                                                \
    _Pragma("unroll") for (int s = 0; s < 4; s++)                              \
        aR[s] = *reinterpret_cast<const float4*>(                              \
            XPTR + (size_t)(m0 + s * 32 + ldrow) * DIMC + ldcg * 4);           \
    _Pragma("unroll") for (int s = 0; s < 2; s++)                              \
        bR[s] = *reinterpret_cast<const float4*>(                              \
            WPTR + (size_t)(j0 + s * 32 + ldrow) * DIMC + ldcg * 4);           \
    _Pragma("unroll") for (int s = 0; s < 4; s++) {                            \
        const int ba = (s * 32 + ldrow) * AST + ldoff;                         \
        As[0][ba + 0] = f2tf(aR[s].x); As[0][ba + 2] = f2tf(aR[s].y);          \
        As[0][ba + 4] = f2tf(aR[s].z); As[0][ba + 6] = f2tf(aR[s].w);          \
    }                                                                          \
    _Pragma("unroll") for (int s = 0; s < 2; s++) {                            \
        const int ba = (s * 32 + ldrow) * AST + ldoff;                         \
        Bs[0][ba + 0] = f2tf(bR[s].x); Bs[0][ba + 2] = f2tf(bR[s].y);          \
        Bs[0][ba + 4] = f2tf(bR[s].z); Bs[0][ba + 6] = f2tf(bR[s].w);          \
    }                                                                          \
    __syncthreads();                                                           \
    for (int t = 0; t < NCH; t++) {                                            \
        const int buf = t & 1;                                                 \
        if (t + 1 < NCH) {                                                     \
            const int kb = (t + 1) * BKC;                                      \
            _Pragma("unroll") for (int s = 0; s < 4; s++)                      \
                aR[s] = *reinterpret_cast<const float4*>(                      \
                    XPTR + (size_t)(m0 + s * 32 + ldrow) * DIMC + kb + ldcg * 4); \
            _Pragma("unroll") for (int s = 0; s < 2; s++)                      \
                bR[s] = *reinterpret_cast<const float4*>(                      \
                    WPTR + (size_t)(j0 + s * 32 + ldrow) * DIMC + kb + ldcg * 4); \
        }                                                                      \
        _Pragma("unroll") for (int ks = 0; ks < 2; ks++) {                     \
            uint2 afr[2][2];                                                   \
            _Pragma("unroll") for (int am = 0; am < 2; am++) {                 \
                const int r0 = wm + am * 16 + frow;                            \
                afr[am][0] = *reinterpret_cast<const uint2*>(                  \
                    &As[buf][r0 * AST + (ks * 4 + fcol) * 2]);                 \
                afr[am][1] = *reinterpret_cast<const uint2*>(                  \
                    &As[buf][(r0 + 8) * AST + (ks * 4 + fcol) * 2]);           \
            }                                                                  \
            uint2 bfr[8];                                                      \
            _Pragma("unroll") for (int an = 0; an < 8; an++)                   \
                bfr[an] = *reinterpret_cast<const uint2*>(                     \
                    &Bs[buf][(an * 8 + frow) * AST + (ks * 4 + fcol) * 2]);    \
            _Pragma("unroll") for (int am = 0; am < 2; am++)                   \
                _Pragma("unroll") for (int an = 0; an < 8; an++)               \
                    mma_tf32(acc[am][an],                                      \
                             afr[am][0].x, afr[am][1].x,                       \
                             afr[am][0].y, afr[am][1].y,                       \
                             bfr[an].x, bfr[an].y);                            \
        }                                                                      \
        if (t + 1 < NCH) {                                                     \
            const int nb = (t + 1) & 1;                                        \
            _Pragma("unroll") for (int s = 0; s < 4; s++) {                    \
                const int ba = (s * 32 + ldrow) * AST + ldoff;                 \
                As[nb][ba + 0] = f2tf(aR[s].x); As[nb][ba + 2] = f2tf(aR[s].y); \
                As[nb][ba + 4] = f2tf(aR[s].z); As[nb][ba + 6] = f2tf(aR[s].w); \
            }                                                                  \
            _Pragma("unroll") for (int s = 0; s < 2; s++) {                    \
                const int ba = (s * 32 + ldrow) * AST + ldoff;                 \
                Bs[nb][ba + 0] = f2tf(bR[s].x); Bs[nb][ba + 2] = f2tf(bR[s].y); \
                Bs[nb][ba + 4] = f2tf(bR[s].z); Bs[nb][ba + 6] = f2tf(bR[s].w); \
            }                                                                  \
            __syncthreads();                                                   \
        }                                                                      \
    }

// ---------------------------------------------------------------------------
// Kernel 0: precompute bias+mask table
// ---------------------------------------------------------------------------
__global__ __launch_bounds__(256)
void bias_kernel(const float* __restrict__ mask,
                 const float* __restrict__ rpb,
                 const int*   __restrict__ rel_idx)
{
    const int wh = blockIdx.x;
    const int w  = wh / NH;
    const int h  = wh - w * NH;
    float* dst = g_bm + (size_t)wh * (NTOK * BMS);
    const float* msk = mask + (size_t)w * (NTOK * NTOK);
    for (int idx = threadIdx.x; idx < NTOK * NTOK; idx += 256) {
        const int i = idx / NTOK;
        const int j = idx - i * NTOK;
        dst[i * BMS + j] = rpb[rel_idx[idx] * NH + h] + msk[idx];
    }
}

// ---------------------------------------------------------------------------
// Kernel 1: QKV GEMM + bias, scatter into g_q/g_k/g_v [B,H,N,hd], q *= scale
// ---------------------------------------------------------------------------
__global__ __launch_bounds__(128, 3)
void qkv_gemm_kernel(const float* __restrict__ X,
                     const float* __restrict__ W,
                     const float* __restrict__ bias)
{
    TF32_GEMM_MAINLOOP(X, W)

    const int tt = j0 / DIMC;
    const int r0 = j0 - tt * DIMC;
    float* dstArr = (tt == 0) ? g_q : ((tt == 1) ? g_k : g_v);
    const float mul = (tt == 0) ? 0.17677669529663687f : 1.0f;

#pragma unroll
    for (int an = 0; an < 8; an++) {
        const int jc = an * 8 + fcol * 2;
        const float bx = bias[j0 + jc];
        const float by = bias[j0 + jc + 1];
        const int c = r0 + jc;
        const int h = c >> 5;
        const int d = c & 31;
#pragma unroll
        for (int am = 0; am < 2; am++) {
#pragma unroll
            for (int rh = 0; rh < 2; rh++) {
                const int m  = m0 + wm + am * 16 + frow + rh * 8;
                const int bi = m / NTOK;
                const int ni = m - bi * NTOK;
                const size_t dst = ((size_t)(bi * NH + h) * NTOK + ni) * HD + d;
                float2 o;
                o.x = (acc[am][an][rh * 2 + 0] + bx) * mul;
                o.y = (acc[am][an][rh * 2 + 1] + by) * mul;
                *reinterpret_cast<float2*>(&dstArr[dst]) = o;
            }
        }
    }
}

// ---------------------------------------------------------------------------
// Kernel 3: output projection  out = ctx @ proj_w.T + proj_b
// ---------------------------------------------------------------------------
__global__ __launch_bounds__(128, 3)
void proj_gemm_kernel(const float* __restrict__ W,
                      const float* __restrict__ bias,
                      float* __restrict__ out)
{
    const float* Xg = g_ctx;
    TF32_GEMM_MAINLOOP(Xg, W)

#pragma unroll
    for (int an = 0; an < 8; an++) {
        const int jc = an * 8 + fcol * 2;
        const float bx = bias[j0 + jc];
        const float by = bias[j0 + jc + 1];
#pragma unroll
        for (int am = 0; am < 2; am++) {
#pragma unroll
            for (int rh = 0; rh < 2; rh++) {
                const int m = m0 + wm + am * 16 + frow + rh * 8;
                float2 o;
                o.x = acc[am][an][rh * 2 + 0] + bx;
                o.y = acc[am][an][rh * 2 + 1] + by;
                *reinterpret_cast<float2*>(&out[(size_t)m * DIMC + j0 + jc]) = o;
            }
        }
    }
}

// ---------------------------------------------------------------------------
// Kernel 2: per-(window, head) attention, fp32 (f32x2).
// S: 4x4 register blocking. PV: 4 rows x 4 d-values per thread — v loads
// broadcast across row-groups, p loads broadcast across d-groups.
// ---------------------------------------------------------------------------
#define QSTR 34
#define SSTR 100

__global__ __launch_bounds__(256)
void attn_kernel(float* __restrict__ attn_out)
{
    __shared__ float qs[NTOK * QSTR];
    __shared__ float ks[NTOK * QSTR];
    __shared__ float vs[NTOK * QSTR];
    __shared__ float Sd[NTOK * SSTR];   // duplicated pairs: Sd[i*100+2j]==[..+1]

    const int bh  = blockIdx.x;
    const int b   = bh / NH;
    const int h   = bh - b * NH;
    const int tid = threadIdx.x;

    // ---- stage q/k/v as float2 ----
    const size_t base2 = (size_t)bh * (NTOK * HD / 2);
    const float2* q2 = reinterpret_cast<const float2*>(g_q) + base2;
    const float2* k2 = reinterpret_cast<const float2*>(g_k) + base2;
    const float2* v2 = reinterpret_cast<const float2*>(g_v) + base2;
    for (int idx = tid; idx < NTOK * (HD / 2); idx += 256) {
        const int r = idx >> 4, dp = idx & 15;
        *reinterpret_cast<float2*>(&qs[r * QSTR + 2 * dp]) = q2[idx];
        *reinterpret_cast<float2*>(&ks[r * QSTR + 2 * dp]) = k2[idx];
        *reinterpret_cast<float2*>(&vs[r * QSTR + 2 * dp]) = v2[idx];
    }
    __syncthreads();

    // ---- S = q k^T + bm : 4x4 register-blocked, one task per thread ----
    const float* bm = g_bm + (size_t)((b & (NWIN - 1)) * NH + h) * (NTOK * BMS);
    if (tid < 13 * 13) {
        const int bi = tid / 13, bj = tid - 13 * (tid / 13);
        const int i0 = bi * 4, j0 = bj * 4;
        const u64* qp[4]; const u64* kp[4];
#pragma unroll
        for (int t = 0; t < 4; t++) {
            const int ri = (i0 + t < NTOK) ? (i0 + t) : (NTOK - 1);
            const int rj = (j0 + t < NTOK) ? (j0 + t) : (NTOK - 1);
            qp[t] = reinterpret_cast<const u64*>(&qs[ri * QSTR]);
            kp[t] = reinterpret_cast<const u64*>(&ks[rj * QSTR]);
        }
        u64 acc[4][4];
#pragma unroll
        for (int a = 0; a < 4; a++)
#pragma unroll
            for (int c = 0; c < 4; c++) acc[a][c] = 0ull;
#pragma unroll
        for (int d = 0; d < HD / 2; d++) {
            u64 qv[4], kv[4];
#pragma unroll
            for (int t = 0; t < 4; t++) { qv[t] = qp[t][d]; kv[t] = kp[t][d]; }
#pragma unroll
            for (int a = 0; a < 4; a++)
#pragma unroll
                for (int c = 0; c < 4; c++)
                    ffma2(acc[a][c], qv[a], kv[c]);
        }
#pragma unroll
        for (int a = 0; a < 4; a++) {
            const int i = i0 + a;
            if (i < NTOK) {
                const float4 bmv = *reinterpret_cast<const float4*>(&bm[i * BMS + j0]);
                const float bb[4] = {bmv.x, bmv.y, bmv.z, bmv.w};
#pragma unroll
                for (int c = 0; c < 4; c++) {
                    if (j0 + c < NTOK) {
                        float2 f = *reinterpret_cast<float2*>(&acc[a][c]);
                        const float s = f.x + f.y + bb[c];
                        float2 dd; dd.x = s; dd.y = s;
                        *reinterpret_cast<float2*>(&Sd[i * SSTR + 2 * (j0 + c)]) = dd;
                    }
                }
            }
        }
    }
    __syncthreads();

    // ---- row softmax (warp per row, 8 warps striding), write attn ----
    const int lane = tid & 31;
    const int wid  = tid >> 5;
    for (int i = wid; i < NTOK; i += 8) {
        float mval = -3.4e38f;
        for (int j = lane; j < NTOK; j += 32) mval = fmaxf(mval, Sd[i * SSTR + 2 * j]);
#pragma unroll
        for (int o = 16; o > 0; o >>= 1)
            mval = fmaxf(mval, __shfl_xor_sync(0xffffffffu, mval, o));
        float sum = 0.f;
        float ev[2];
        for (int j = lane, c = 0; j < NTOK; j += 32, c++) {
            const float e = __expf(Sd[i * SSTR + 2 * j] - mval);
            ev[c] = e;
            sum += e;
        }
#pragma unroll
        for (int o = 16; o > 0; o >>= 1)
            sum += __shfl_xor_sync(0xffffffffu, sum, o);
        const float inv = 1.0f / sum;
        for (int j = lane, c = 0; j < NTOK; j += 32, c++) {
            const float pv = ev[c] * inv;
            float2 dd; dd.x = pv; dd.y = pv;
            *reinterpret_cast<float2*>(&Sd[i * SSTR + 2 * j]) = dd;
            if (attn_out)
                attn_out[(size_t)bh * (NTOK * NTOK) + i * NTOK + j] = pv;
        }
    }
    __syncthreads();

    // ---- ctx = P V : 4 rows x 4 d-values per thread (13*8 = 104 tasks) ----
    if (tid < 13 * 8) {
        const int rb = tid >> 3;          // 0..12 : rows 4rb..4rb+3
        const int dg = tid & 7;           // 0..7  : d 4dg..4dg+3
        const int i0 = rb * 4;
        const int r1 = (i0 + 1 < NTOK) ? i0 + 1 : NTOK - 1;
        const int r2 = (i0 + 2 < NTOK) ? i0 + 2 : NTOK - 1;
        const int r3 = (i0 + 3 < NTOK) ? i0 + 3 : NTOK - 1;
        u64 c00 = 0, c01 = 0, c10 = 0, c11 = 0;
        u64 c20 = 0, c21 = 0, c30 = 0, c31 = 0;
#pragma unroll 7
        for (int j = 0; j < NTOK; j++) {
            const u64 v0 = *reinterpret_cast<const u64*>(&vs[j * QSTR + 4 * dg]);
            const u64 v1 = *reinterpret_cast<const u64*>(&vs[j * QSTR + 4 * dg + 2]);
            const u64 p0 = *reinterpret_cast<const u64*>(&Sd[i0 * SSTR + 2 * j]);
            const u64 p1 = *reinterpret_cast<const u64*>(&Sd[r1 * SSTR + 2 * j]);
            const u64 p2 = *reinterpret_cast<const u64*>(&Sd[r2 * SSTR + 2 * j]);
            const u64 p3 = *reinterpret_cast<const u64*>(&Sd[r3 * SSTR + 2 * j]);
            ffma2(c00, p0, v0); ffma2(c01, p0, v1);
            ffma2(c10, p1, v0); ffma2(c11, p1, v1);
            ffma2(c20, p2, v0); ffma2(c21, p2, v1);
            ffma2(c30, p3, v0); ffma2(c31, p3, v1);
        }
        const size_t ob = (size_t)b * NTOK * DIMC + h * HD + 4 * dg;
        {
            float2 lo = *reinterpret_cast<float2*>(&c00);
            float2 hi = *reinterpret_cast<float2*>(&c01);
            *reinterpret_cast<float4*>(&g_ctx[ob + (size_t)i0 * DIMC]) =
                make_float4(lo.x, lo.y, hi.x, hi.y);
        }
        if (i0 + 1 < NTOK) {
            float2 lo = *reinterpret_cast<float2*>(&c10);
            float2 hi = *reinterpret_cast<float2*>(&c11);
            *reinterpret_cast<float4*>(&g_ctx[ob + (size_t)(i0 + 1) * DIMC]) =
                make_float4(lo.x, lo.y, hi.x, hi.y);
        }
        if (i0 + 2 < NTOK) {
            float2 lo = *reinterpret_cast<float2*>(&c20);
            float2 hi = *reinterpret_cast<float2*>(&c21);
            *reinterpret_cast<float4*>(&g_ctx[ob + (size_t)(i0 + 2) * DIMC]) =
                make_float4(lo.x, lo.y, hi.x, hi.y);
        }
        if (i0 + 3 < NTOK) {
            float2 lo = *reinterpret_cast<float2*>(&c30);
            float2 hi = *reinterpret_cast<float2*>(&c31);
            *reinterpret_cast<float4*>(&g_ctx[ob + (size_t)(i0 + 3) * DIMC]) =
                make_float4(lo.x, lo.y, hi.x, hi.y);
        }
    }
}

// ---------------------------------------------------------------------------
// Launch
// ---------------------------------------------------------------------------
extern "C" void kernel_launch(void* const* d_in, const int* in_sizes, int n_in,
                              void* d_out, int out_size)
{
    const float* x      = (const float*)d_in[0];
    const float* mask   = (const float*)d_in[1];
    const float* qkv_w  = (const float*)d_in[2];
    const float* qkv_b  = (const float*)d_in[3];
    const float* proj_w = (const float*)d_in[4];
    const float* proj_b = (const float*)d_in[5];
    const float* rpb    = (const float*)d_in[6];
    const int*   relidx = (const int*)d_in[7];

    float* out = (float*)d_out;
    const long OUT_ELEMS  = (long)B_ * NTOK * DIMC;          // 38,535,168
    const long ATTN_ELEMS = (long)B_ * NH * NTOK * NTOK;     // 59,006,976
    float* attn_out = nullptr;
    if ((long)out_size >= OUT_ELEMS + ATTN_ELEMS) attn_out = out + OUT_ELEMS;

    bias_kernel<<<NWIN * NH, 256>>>(mask, rpb, relidx);
    qkv_gemm_kernel<<<dim3(576 / BN, (B_ * NTOK) / BM), 128>>>(x, qkv_w, qkv_b);
    attn_kernel<<<B_ * NH, 256>>>(attn_out);
    proj_gemm_kernel<<<dim3(DIMC / BN, (B_ * NTOK) / BM), 128>>>(proj_w, proj_b, out);

    (void)in_sizes; (void)n_in;
}